// round 15
// baseline (speedup 1.0000x reference)
#include <cuda_runtime.h>
#include <cuda_bf16.h>
#include <math.h>

// ---------------- problem constants ----------------
#define NIMG 4
#define BATCH 8
#define SEQ 576
#define DIM 256
#define NHEAD 8
#define DHEAD 32
#define NLAYER 6
#define MLPDIM 512
#define NB (NIMG*BATCH)      // 32
#define TOK (NB*SEQ)         // 18432
#define KPATCH 768           // 3*16*16
#define GRID24 24

// ---------------- scratch (device globals; no allocation allowed) ----------------
__device__ __nv_bfloat16 g_imh[(long)NIMG*BATCH*SEQ*KPATCH];
__device__ __nv_bfloat16 g_iml[(long)NIMG*BATCH*SEQ*KPATCH];
__device__ __nv_bfloat16 g_peh[(long)TOK*DIM];
__device__ __nv_bfloat16 g_pel[(long)TOK*DIM];
__device__ __nv_bfloat16 g_oh [(long)TOK*DIM];
__device__ __nv_bfloat16 g_ol [(long)TOK*DIM];
__device__ __nv_bfloat16 g_cwh[(long)NIMG*DIM*KPATCH];
__device__ __nv_bfloat16 g_cwl[(long)NIMG*DIM*KPATCH];
__device__ __nv_bfloat16 g_iwh[(long)NLAYER*3*DIM*DIM];
__device__ __nv_bfloat16 g_iwl[(long)NLAYER*3*DIM*DIM];
__device__ __nv_bfloat16 g_owh[(long)NLAYER*DIM*DIM];
__device__ __nv_bfloat16 g_owl[(long)NLAYER*DIM*DIM];
__device__ float g_qkv[(long)TOK*3*DIM];                 // 56.6 MB (K/V f32; Q unused)
__device__ unsigned g_q2[(long)TOK*512];                 // 37.7 MB Q*SC tf32 {hi,lo} pairs
__device__ float g_pe [(long)TOK*DIM];                   // 18.9 MB
// pre-converted attention operands (written by cvt_kv each layer)
__device__ unsigned      g_kt [(long)NB*NHEAD*32*SEQ];   // K^T tf32 [nb*h][dh][key]
__device__ __nv_bfloat16 g_vth[(long)NB*NHEAD*32*SEQ];   // V^T bf16 hi [nb*h][dh][key]
__device__ __nv_bfloat16 g_vtl[(long)NB*NHEAD*32*SEQ];   // V^T bf16 lo
__device__ float g_feat[BATCH*NIMG*DIM];

// ---------------- helpers ----------------
__device__ __forceinline__ unsigned f2tf(float f) {
    unsigned u; asm("cvt.rna.tf32.f32 %0, %1;" : "=r"(u) : "f"(f)); return u;
}
__device__ __forceinline__ void mma_tf32(float* d, const unsigned* a, unsigned b0, unsigned b1) {
    asm volatile(
        "mma.sync.aligned.m16n8k8.row.col.f32.tf32.tf32.f32 "
        "{%0,%1,%2,%3},{%4,%5,%6,%7},{%8,%9},{%0,%1,%2,%3};"
        : "+f"(d[0]), "+f"(d[1]), "+f"(d[2]), "+f"(d[3])
        : "r"(a[0]), "r"(a[1]), "r"(a[2]), "r"(a[3]), "r"(b0), "r"(b1));
}
__device__ __forceinline__ void mma_bf16(float* d, const unsigned* a, unsigned b0, unsigned b1) {
    asm volatile(
        "mma.sync.aligned.m16n8k16.row.col.f32.bf16.bf16.f32 "
        "{%0,%1,%2,%3},{%4,%5,%6,%7},{%8,%9},{%0,%1,%2,%3};"
        : "+f"(d[0]), "+f"(d[1]), "+f"(d[2]), "+f"(d[3])
        : "r"(a[0]), "r"(a[1]), "r"(a[2]), "r"(a[3]), "r"(b0), "r"(b1));
}
__device__ __forceinline__ void mma_bf16_k8(float* d, const unsigned* a, unsigned b0) {
    asm volatile(
        "mma.sync.aligned.m16n8k8.row.col.f32.bf16.bf16.f32 "
        "{%0,%1,%2,%3},{%4,%5},{%6},{%0,%1,%2,%3};"
        : "+f"(d[0]), "+f"(d[1]), "+f"(d[2]), "+f"(d[3])
        : "r"(a[0]), "r"(a[1]), "r"(b0));
}
__device__ __forceinline__ void ldsm4(unsigned* r, unsigned addr) {
    asm volatile("ldmatrix.sync.aligned.m8n8.x4.shared.b16 {%0,%1,%2,%3}, [%4];"
        : "=r"(r[0]), "=r"(r[1]), "=r"(r[2]), "=r"(r[3]) : "r"(addr));
}
__device__ __forceinline__ void cp16(void* smem, const void* g) {
    unsigned s = (unsigned)__cvta_generic_to_shared(smem);
    asm volatile("cp.async.ca.shared.global [%0], [%1], 16;\n" :: "r"(s), "l"(g));
}
__device__ __forceinline__ void splitbf(float v, __nv_bfloat16& h, __nv_bfloat16& l) {
    h = __float2bfloat16(v);
    l = __float2bfloat16(v - __bfloat162float(h));
}

// ---------------- weight split kernel ----------------
__global__ void cvt_bf(const float* __restrict__ s,
                       __nv_bfloat16* __restrict__ h, __nv_bfloat16* __restrict__ l, int n) {
    int i = blockIdx.x*256 + threadIdx.x;
    if (i >= n) return;
    splitbf(s[i], h[i], l[i]);
}

// ---------------- im2col (split bf16 planes); grid (3, SEQ, NB) ----------------
__global__ void im2col_k(const float* __restrict__ x) {
    int k  = blockIdx.x*256 + threadIdx.x;     // 0..767
    int s  = blockIdx.y;                       // 0..575
    int z  = blockIdx.z;                       // ni*BATCH + b
    int ni = z >> 3, b = z & 7;
    int c  = k >> 8;
    int py = (k >> 4) & 15;
    int px = k & 15;
    int gy = s / GRID24, gx = s - gy*GRID24;
    float v = x[(((long)b*12 + ni*3 + c)*384 + gy*16 + py)*384 + gx*16 + px];
    long idx = (((long)z*SEQ) + s)*KPATCH + k;
    splitbf(v, g_imh[idx], g_iml[idx]);
}

// ---------------- K/V transpose+convert (coalesced both sides, smem transpose) ----------------
#define CH 64
__global__ __launch_bounds__(256) void cvt_kv(const float* __restrict__ qkv) {
    int h = blockIdx.x, nb = blockIdx.y;
    __shared__ __align__(16) unsigned       sk [32][CH+4];
    __shared__ __align__(16) unsigned short svh[32][CH+8];
    __shared__ __align__(16) unsigned short svl[32][CH+8];
    const int t = threadIdx.x;
    const int lane = t & 31, wrp = t >> 5;
    const long base  = ((long)nb*SEQ)*768 + 256 + h*32 + lane;
    const long obase = (long)(nb*NHEAD + h)*32;
    const int dh = t >> 3, c8 = (t & 7)*8;

    for (int kb = 0; kb < SEQ; kb += CH) {
        #pragma unroll
        for (int i = 0; i < 8; i++) {
            int kc = wrp + i*8;
            long rp = base + (long)(kb + kc)*768;
            float kv = qkv[rp];
            float vv = qkv[rp + 256];
            sk[lane][kc] = f2tf(kv);
            __nv_bfloat16 hh, ll; splitbf(vv, hh, ll);
            svh[lane][kc] = *(unsigned short*)&hh;
            svl[lane][kc] = *(unsigned short*)&ll;
        }
        __syncthreads();
        {
            unsigned* dst = g_kt + (obase + dh)*SEQ + kb + c8;
            *(uint4*)dst       = *(const uint4*)&sk[dh][c8];
            *(uint4*)(dst + 4) = *(const uint4*)&sk[dh][c8 + 4];
            *(uint4*)(g_vth + (obase + dh)*SEQ + kb + c8) = *(const uint4*)&svh[dh][c8];
            *(uint4*)(g_vtl + (obase + dh)*SEQ + kb + c8) = *(const uint4*)&svl[dh][c8];
        }
        __syncthreads();
    }
}

// ---------------- bf16x3 tensor GEMM: ldmatrix + reg double-buffer ----------------
// mode 0: Cf (opt f32) + Ch/Cl split planes. mode 1 (qkv): n<256 -> g_q2 scaled
// tf32 pairs; n>=256 -> Cf f32 (K/V region of g_qkv).
#define BSTR 40
__global__ __launch_bounds__(256) void gemm_bf3(
    const __nv_bfloat16* __restrict__ Ah, const __nv_bfloat16* __restrict__ Al,
    const __nv_bfloat16* __restrict__ Bh, const __nv_bfloat16* __restrict__ Bl,
    float* __restrict__ Cf, __nv_bfloat16* __restrict__ Ch, __nv_bfloat16* __restrict__ Cl,
    int M, int N, int K,
    const float* __restrict__ bias, const float* __restrict__ pos,
    long strideA, long strideB, long strideC, int strideBias, int mode)
{
    Ah += (long)blockIdx.z * strideA;  Al += (long)blockIdx.z * strideA;
    Bh += (long)blockIdx.z * strideB;  Bl += (long)blockIdx.z * strideB;
    if (Cf) Cf += (long)blockIdx.z * strideC;
    if (Ch) { Ch += (long)blockIdx.z * strideC; Cl += (long)blockIdx.z * strideC; }
    if (bias) bias += (long)blockIdx.z * strideBias;

    __shared__ __nv_bfloat16 sAh[64][BSTR], sAl[64][BSTR];
    __shared__ __nv_bfloat16 sBh[64][BSTR], sBl[64][BSTR];

    const int tid  = threadIdx.x;
    const int lane = tid & 31;
    const int w    = tid >> 5;
    const int r4   = lane >> 2;
    const int c4   = lane & 3;
    const int wm   = w & 3, wn = w >> 2;
    const int m0   = blockIdx.y * 64, n0 = blockIdx.x * 64;
    const int lrow = tid >> 2;
    const int lk8  = (tid & 3) * 8;

    const int a_row = wm*16 + (lane & 15);
    const int a_col = (lane >> 4) * 8;
    const unsigned aAh = (unsigned)__cvta_generic_to_shared(&sAh[a_row][a_col]);
    const unsigned aAl = (unsigned)__cvta_generic_to_shared(&sAl[a_row][a_col]);
    const int b_rb = wn*32 + (lane & 7) + ((lane >> 4) << 3);
    const int b_cb = ((lane >> 3) & 1) * 8;
    const unsigned bBh0 = (unsigned)__cvta_generic_to_shared(&sBh[b_rb][b_cb]);
    const unsigned bBl0 = (unsigned)__cvta_generic_to_shared(&sBl[b_rb][b_cb]);
    const unsigned tstep = 16*BSTR*2;

    const __nv_bfloat16* pAh = &Ah[(long)(m0 + lrow)*K + lk8];
    const __nv_bfloat16* pAl = &Al[(long)(m0 + lrow)*K + lk8];
    const __nv_bfloat16* pBh = &Bh[(long)(n0 + lrow)*K + lk8];
    const __nv_bfloat16* pBl = &Bl[(long)(n0 + lrow)*K + lk8];

    float acc[4][4] = {};
    uint4 rah = *(const uint4*)&pAh[0], ral = *(const uint4*)&pAl[0];
    uint4 rbh = *(const uint4*)&pBh[0], rbl = *(const uint4*)&pBl[0];

    for (int k0 = 0; k0 < K; k0 += 32) {
        *(uint4*)&sAh[lrow][lk8] = rah; *(uint4*)&sAl[lrow][lk8] = ral;
        *(uint4*)&sBh[lrow][lk8] = rbh; *(uint4*)&sBl[lrow][lk8] = rbl;
        __syncthreads();
        if (k0 + 32 < K) {
            rah = *(const uint4*)&pAh[k0+32]; ral = *(const uint4*)&pAl[k0+32];
            rbh = *(const uint4*)&pBh[k0+32]; rbl = *(const uint4*)&pBl[k0+32];
        }
        #pragma unroll
        for (int kk = 0; kk < 2; kk++) {
            const unsigned koff = kk*32;
            unsigned ah[4], al[4];
            ldsm4(ah, aAh + koff);
            ldsm4(al, aAl + koff);
            #pragma unroll
            for (int t = 0; t < 2; t++) {
                unsigned bh[4], bl[4];
                ldsm4(bh, bBh0 + t*tstep + koff);
                ldsm4(bl, bBl0 + t*tstep + koff);
                mma_bf16(acc[2*t],   ah, bh[0], bh[1]);
                mma_bf16(acc[2*t],   al, bh[0], bh[1]);
                mma_bf16(acc[2*t],   ah, bl[0], bl[1]);
                mma_bf16(acc[2*t+1], ah, bh[2], bh[3]);
                mma_bf16(acc[2*t+1], al, bh[2], bh[3]);
                mma_bf16(acc[2*t+1], ah, bl[2], bl[3]);
            }
        }
        __syncthreads();
    }

    const float SCq = 0.17677669529663687f;   // 1/sqrt(32)
    #pragma unroll
    for (int nt = 0; nt < 4; nt++) {
        int n = n0 + wn*32 + nt*8 + c4*2;
        float bx = 0.f, by = 0.f;
        if (bias) { bx = bias[n]; by = bias[n+1]; }
        int row0 = m0 + wm*16 + r4, row1 = row0 + 8;
        float v00 = acc[nt][0]+bx, v01 = acc[nt][1]+by;
        float v10 = acc[nt][2]+bx, v11 = acc[nt][3]+by;
        if (mode == 1) {
            if (n < DIM) {
                v00 *= SCq; v01 *= SCq; v10 *= SCq; v11 *= SCq;
                unsigned h00=f2tf(v00), h01=f2tf(v01), h10=f2tf(v10), h11=f2tf(v11);
                uint4 p0 = make_uint4(h00, f2tf(v00-__uint_as_float(h00)),
                                      h01, f2tf(v01-__uint_as_float(h01)));
                uint4 p1 = make_uint4(h10, f2tf(v10-__uint_as_float(h10)),
                                      h11, f2tf(v11-__uint_as_float(h11)));
                *(uint4*)&g_q2[(long)row0*512 + n*2] = p0;
                *(uint4*)&g_q2[(long)row1*512 + n*2] = p1;
            } else {
                *(float2*)&Cf[(long)row0*N + n] = make_float2(v00, v01);
                *(float2*)&Cf[(long)row1*N + n] = make_float2(v10, v11);
            }
        } else {
            if (pos) {
                const float* p0 = pos + (long)(row0 % SEQ)*DIM + n;
                const float* p1 = pos + (long)(row1 % SEQ)*DIM + n;
                v00 += p0[0]; v01 += p0[1]; v10 += p1[0]; v11 += p1[1];
            }
            if (Cf) {
                *(float2*)&Cf[(long)row0*N + n] = make_float2(v00, v01);
                *(float2*)&Cf[(long)row1*N + n] = make_float2(v10, v11);
            }
            if (Ch) {
                __nv_bfloat162 h0, l0, h1, l1;
                splitbf(v00, h0.x, l0.x); splitbf(v01, h0.y, l0.y);
                splitbf(v10, h1.x, l1.x); splitbf(v11, h1.y, l1.y);
                *(__nv_bfloat162*)&Ch[(long)row0*N + n] = h0;
                *(__nv_bfloat162*)&Cl[(long)row0*N + n] = l0;
                *(__nv_bfloat162*)&Ch[(long)row1*N + n] = h1;
                *(__nv_bfloat162*)&Cl[(long)row1*N + n] = l1;
            }
        }
    }
}

// ---------------- fused attention: cp.async P1 + pre-split Q + ldmatrix PV ----------------
#define KSTRD 580
#define VSTR  292
#define ATTN_FLOATS (32*KSTRD + 2*32*VSTR + 256 + 32 + 32)
#define ATTN_SMEM (ATTN_FLOATS*4)   // 150,272 B

__global__ __launch_bounds__(512, 1) void attn_mma(
    float* __restrict__ attn_out, int layer)
{
    extern __shared__ float sm[];
    unsigned* Kt   = (unsigned*)sm;                  // [32 dh][580] tf32 K^T; buf overlay
    unsigned* Vh   = Kt + 32*KSTRD;                  // [32 dh][292] bf16-pair V^T hi
    unsigned* Vl   = Vh + 32*VSTR;                   // [32 dh][292] bf16-pair V^T lo
    float* pbufA   = sm + 32*KSTRD + 2*32*VSTR;      // [32][8]
    float* rowmax  = pbufA + 256;                    // [32]
    float* rinv    = rowmax + 32;                    // [32]
    float* buf     = (float*)Kt;                     // PV partial-O scratch (32 KB)

    const int tid  = threadIdx.x;
    const int lane = tid & 31;
    const int w    = tid >> 5;                  // 0..15
    const int r4   = lane >> 2;
    const int c4   = lane & 3;
    const int ws   = w >> 3;                    // q-subtile (16 q)
    const int wk   = w & 7;                     // key-slice (72 keys)
    const int qt   = blockIdx.x;                // 0..17
    const int nb   = blockIdx.y;                // 0..31

    // P1 copy assignments
    const int kdh = tid >> 4, kci = tid & 15;
    const int vp  = tid >> 8, vrem = tid & 255;
    const int vdh = vrem >> 3, vci = vrem & 7;
    // PV ldmatrix base
    const unsigned vb_h = (unsigned)__cvta_generic_to_shared(&Vh[lane*VSTR + wk*36]);
    const unsigned vb_l = (unsigned)__cvta_generic_to_shared(&Vl[lane*VSTR + wk*36]);

    const long qrow = (long)(nb*SEQ + qt*32 + ws*16 + r4);

    float am[9][4];
    #pragma unroll
    for (int nt = 0; nt < 9; nt++)
        #pragma unroll
        for (int i = 0; i < 4; i++) am[nt][i] = 0.f;

    for (int h = 0; h < NHEAD; h++) {
        // ---- P1: cp.async copies of pre-converted K^T / V^T ----
        {
            const long kvb = (long)(nb*NHEAD + h)*32;
            const unsigned* gK = g_kt + (kvb + kdh)*SEQ;
            unsigned* dK = Kt + kdh*KSTRD;
            #pragma unroll
            for (int j = 0; j < 9; j++) {
                int c4i = (kci + j*16)*4;
                cp16(&dK[c4i], &gK[c4i]);
            }
            const __nv_bfloat16* gV = (vp ? g_vtl : g_vth) + (kvb + vdh)*SEQ;
            unsigned* dV = (vp ? Vl : Vh) + vdh*VSTR;
            #pragma unroll
            for (int j = 0; j < 9; j++) {
                int cc = vci + j*8;
                cp16(&dV[cc*4], &gV[cc*8]);
            }
            asm volatile("cp.async.commit_group;\n");
            asm volatile("cp.async.wait_group 0;\n");
        }
        __syncthreads();                        // S1

        // ---- P2: S = Q K^T (Q pre-split pairs); warp (ws,wk) -> 16q x 72k ----
        float acc[9][4];
        #pragma unroll
        for (int nt = 0; nt < 9; nt++)
            #pragma unroll
            for (int i = 0; i < 4; i++) acc[nt][i] = 0.f;

        #pragma unroll
        for (int kc = 0; kc < 4; kc++) {
            unsigned ah[4], al[4];
            {
                const unsigned* qp = g_q2 + qrow*512 + (h*32 + kc*8 + c4)*2;
                uint2 qa = *(const uint2*)qp;
                uint2 qb = *(const uint2*)(qp + 8*512);
                uint2 qc = *(const uint2*)(qp + 8);
                uint2 qd = *(const uint2*)(qp + 8*512 + 8);
                ah[0]=qa.x; ah[1]=qb.x; ah[2]=qc.x; ah[3]=qd.x;
                al[0]=qa.y; al[1]=qb.y; al[2]=qc.y; al[3]=qd.y;
            }
            const unsigned* kb  = &Kt[(kc*8 + c4)*KSTRD + wk*72 + r4];
            const unsigned* kb4 = kb + 4*KSTRD;
            #pragma unroll
            for (int nt = 0; nt < 9; nt++) {
                unsigned b0 = kb[nt*8], b1 = kb4[nt*8];
                mma_tf32(acc[nt], ah, b0, b1);
                mma_tf32(acc[nt], al, b0, b1);
            }
        }
        // partial row max
        {
            float pm[2] = {-1e30f, -1e30f};
            #pragma unroll
            for (int nt = 0; nt < 9; nt++) {
                pm[0] = fmaxf(pm[0], fmaxf(acc[nt][0], acc[nt][1]));
                pm[1] = fmaxf(pm[1], fmaxf(acc[nt][2], acc[nt][3]));
            }
            #pragma unroll
            for (int s = 0; s < 2; s++) {
                pm[s] = fmaxf(pm[s], __shfl_xor_sync(0xffffffffu, pm[s], 1));
                pm[s] = fmaxf(pm[s], __shfl_xor_sync(0xffffffffu, pm[s], 2));
            }
            if (c4 == 0) {
                pbufA[(ws*16 + r4)*8 + wk]     = pm[0];
                pbufA[(ws*16 + 8 + r4)*8 + wk] = pm[1];
            }
        }
        __syncthreads();                        // S2
        if (tid < 32) {
            float m = pbufA[tid*8];
            #pragma unroll
            for (int i = 1; i < 8; i++) m = fmaxf(m, pbufA[tid*8 + i]);
            rowmax[tid] = m;
        }
        __syncthreads();                        // S3
        // ---- P4: e = exp(s - rowmax) in registers; row sums ----
        {
            float rm0 = rowmax[ws*16 + r4], rm1 = rowmax[ws*16 + 8 + r4];
            float ps[2] = {0.f, 0.f};
            #pragma unroll
            for (int nt = 0; nt < 9; nt++) {
                float e0 = __expf(acc[nt][0] - rm0);
                float e1 = __expf(acc[nt][1] - rm0);
                float e2 = __expf(acc[nt][2] - rm1);
                float e3 = __expf(acc[nt][3] - rm1);
                acc[nt][0] = e0; acc[nt][1] = e1;
                acc[nt][2] = e2; acc[nt][3] = e3;
                ps[0] += e0 + e1;
                ps[1] += e2 + e3;
            }
            #pragma unroll
            for (int s = 0; s < 2; s++) {
                ps[s] += __shfl_xor_sync(0xffffffffu, ps[s], 1);
                ps[s] += __shfl_xor_sync(0xffffffffu, ps[s], 2);
            }
            if (c4 == 0) {
                pbufA[(ws*16 + r4)*8 + wk]     = ps[0];
                pbufA[(ws*16 + 8 + r4)*8 + wk] = ps[1];
            }
        }
        __syncthreads();                        // S4
        if (tid < 32) {
            float sa = 0.f;
            #pragma unroll
            for (int i = 0; i < 8; i++) sa += pbufA[tid*8 + i];
            rinv[tid] = __frcp_rn(sa);
        }
        __syncthreads();                        // S5
        // ---- P5: Am += e * rinv / 8 (registers) ----
        {
            float ra0 = rinv[ws*16 + r4]*0.125f, ra1 = rinv[ws*16 + 8 + r4]*0.125f;
            #pragma unroll
            for (int nt = 0; nt < 9; nt++) {
                am[nt][0] += acc[nt][0] * ra0;
                am[nt][1] += acc[nt][1] * ra0;
                am[nt][2] += acc[nt][2] * ra1;
                am[nt][3] += acc[nt][3] * ra1;
            }
        }
        // ---- pack E into bf16 hi/lo fragments ----
        unsigned eh[9][2], el[9][2];
        #pragma unroll
        for (int nt = 0; nt < 9; nt++) {
            __nv_bfloat162 h01 = __floats2bfloat162_rn(acc[nt][0], acc[nt][1]);
            __nv_bfloat162 h23 = __floats2bfloat162_rn(acc[nt][2], acc[nt][3]);
            __nv_bfloat162 l01 = __floats2bfloat162_rn(acc[nt][0] - __bfloat162float(h01.x),
                                                       acc[nt][1] - __bfloat162float(h01.y));
            __nv_bfloat162 l23 = __floats2bfloat162_rn(acc[nt][2] - __bfloat162float(h23.x),
                                                       acc[nt][3] - __bfloat162float(h23.y));
            eh[nt][0] = *(unsigned*)&h01; eh[nt][1] = *(unsigned*)&h23;
            el[nt][0] = *(unsigned*)&l01; el[nt][1] = *(unsigned*)&l23;
        }
        // ---- PV via ldmatrix: partial O[16q x 32dh] over this warp's 72 keys ----
        float po[4][4] = {};
        #pragma unroll
        for (int s = 0; s < 4; s++) {
            unsigned a_h[4] = {eh[2*s][0], eh[2*s][1], eh[2*s+1][0], eh[2*s+1][1]};
            unsigned a_l[4] = {el[2*s][0], el[2*s][1], el[2*s+1][0], el[2*s+1][1]};
            unsigned bh0[4], bh1[4], bl0[4], bl1[4];
            ldsm4(bh0, vb_h + s*32);
            ldsm4(bh1, vb_h + s*32 + 16);
            ldsm4(bl0, vb_l + s*32);
            ldsm4(bl1, vb_l + s*32 + 16);
            #pragma unroll
            for (int nt6 = 0; nt6 < 4; nt6++) {
                mma_bf16(po[nt6], a_h, bh0[nt6], bh1[nt6]);
                mma_bf16(po[nt6], a_l, bh0[nt6], bh1[nt6]);
                mma_bf16(po[nt6], a_h, bl0[nt6], bl1[nt6]);
            }
        }
        {   // tail keys 64..71 (k8)
            unsigned bh0[4], bl0[4];
            ldsm4(bh0, vb_h + 128);
            ldsm4(bl0, vb_l + 128);
            #pragma unroll
            for (int nt6 = 0; nt6 < 4; nt6++) {
                mma_bf16_k8(po[nt6], eh[8], bh0[nt6]);
                mma_bf16_k8(po[nt6], el[8], bh0[nt6]);
                mma_bf16_k8(po[nt6], eh[8], bl0[nt6]);
            }
        }
        // ---- store partials into buf (K region; all K reads done since S2) ----
        #pragma unroll
        for (int nt6 = 0; nt6 < 4; nt6++)
            *(float4*)&buf[(((ws*4 + nt6)*8 + wk)*32 + lane)*4] =
                make_float4(po[nt6][0], po[nt6][1], po[nt6][2], po[nt6][3]);
        __syncthreads();                        // S6
        // ---- reduce 8 key-slices; scale; write split bf16 O ----
        if (w < 8) {
            int rws = w >> 2, rnt = w & 3;
            float4 s4 = make_float4(0.f, 0.f, 0.f, 0.f);
            #pragma unroll
            for (int k = 0; k < 8; k++) {
                float4 p = *(const float4*)&buf[(((rws*4 + rnt)*8 + k)*32 + lane)*4];
                s4.x += p.x; s4.y += p.y; s4.z += p.z; s4.w += p.w;
            }
            int q0 = rws*16 + r4;
            int dh = rnt*8 + c4*2;
            float ri0 = rinv[q0], ri1 = rinv[q0 + 8];
            float x0 = s4.x*ri0, x1 = s4.y*ri0;
            float x2 = s4.z*ri1, x3 = s4.w*ri1;
            long orow = (long)(nb*SEQ + qt*32 + q0)*DIM + h*32 + dh;
            __nv_bfloat162 h0, l0, h1, l1;
            splitbf(x0, h0.x, l0.x); splitbf(x1, h0.y, l0.y);
            splitbf(x2, h1.x, l1.x); splitbf(x3, h1.y, l1.y);
            *(__nv_bfloat162*)&g_oh[orow]         = h0;
            *(__nv_bfloat162*)&g_ol[orow]         = l0;
            *(__nv_bfloat162*)&g_oh[orow + 8*DIM] = h1;
            *(__nv_bfloat162*)&g_ol[orow + 8*DIM] = l1;
        }
        __syncthreads();                        // S7: buf reads done before next P1
    }
    // ---- final: head-mean attention from registers ----
    float* aout = attn_out + (long)(layer*NB + nb)*SEQ*SEQ + (long)qt*32*SEQ;
    #pragma unroll
    for (int nt = 0; nt < 9; nt++) {
        int col = wk*72 + nt*8 + c4*2;
        *(float2*)&aout[(long)(ws*16 + r4)*SEQ + col]     = make_float2(am[nt][0], am[nt][1]);
        *(float2*)&aout[(long)(ws*16 + 8 + r4)*SEQ + col] = make_float2(am[nt][2], am[nt][3]);
    }
}

// ---------------- feature mean over sequence ----------------
__global__ void feat_k(void) {
    int ni = blockIdx.x, b = blockIdx.y, d = threadIdx.x;
    const float* p = g_pe + ((long)(ni*BATCH + b)*SEQ)*DIM + d;
    float s = 0.f;
    for (int t = 0; t < SEQ; t++) s += p[(long)t*DIM];
    g_feat[b*(NIMG*DIM) + ni*DIM + d] = s * (1.0f/576.0f);
}

// ---------------- MLP head ----------------
__global__ void head_k(const float* __restrict__ w1, const float* __restrict__ b1,
                       const float* __restrict__ w2, const float* __restrict__ b2,
                       float* __restrict__ out) {
    __shared__ float fs[NIMG*DIM];
    __shared__ float hs[MLPDIM];
    int b = blockIdx.x, tid = threadIdx.x;
    for (int t = tid; t < NIMG*DIM; t += MLPDIM) fs[t] = g_feat[b*NIMG*DIM + t];
    __syncthreads();
    float a = b1[tid];
    const float* wr = w1 + (long)tid*(NIMG*DIM);
    for (int d2 = 0; d2 < NIMG*DIM; d2++) a += fs[d2]*wr[d2];
    hs[tid] = fmaxf(a, 0.f) * w2[tid];
    __syncthreads();
    for (int st = 256; st > 0; st >>= 1) {
        if (tid < st) hs[tid] += hs[tid + st];
        __syncthreads();
    }
    if (tid == 0) out[b] = hs[0] + b2[0];
}

// ---------------- launch ----------------
extern "C" void kernel_launch(void* const* d_in, const int* in_sizes, int n_in,
                              void* d_out, int out_size) {
    const float* x      = (const float*)d_in[0];
    const float* conv_w = (const float*)d_in[1];
    const float* conv_b = (const float*)d_in[2];
    const float* pos_e  = (const float*)d_in[3];
    const float* in_w   = (const float*)d_in[4];
    const float* in_b   = (const float*)d_in[5];
    const float* out_w  = (const float*)d_in[6];
    const float* out_b  = (const float*)d_in[7];
    const float* hw1    = (const float*)d_in[8];
    const float* hb1    = (const float*)d_in[9];
    const float* hw2    = (const float*)d_in[10];
    const float* hb2    = (const float*)d_in[11];

    float* out  = (float*)d_out;            // [8]
    float* attn = out + BATCH;              // [6,4,8,576,576]

    cudaFuncSetAttribute(attn_mma, cudaFuncAttributeMaxDynamicSharedMemorySize, ATTN_SMEM);

    __nv_bfloat16 *imh_p, *iml_p, *peh_p, *pel_p, *oh_p, *ol_p;
    __nv_bfloat16 *cwh_p, *cwl_p, *iwh_p, *iwl_p, *owh_p, *owl_p;
    float *qkv_p, *pe_p;
    cudaGetSymbolAddress((void**)&imh_p, g_imh);
    cudaGetSymbolAddress((void**)&iml_p, g_iml);
    cudaGetSymbolAddress((void**)&peh_p, g_peh);
    cudaGetSymbolAddress((void**)&pel_p, g_pel);
    cudaGetSymbolAddress((void**)&oh_p,  g_oh);
    cudaGetSymbolAddress((void**)&ol_p,  g_ol);
    cudaGetSymbolAddress((void**)&cwh_p, g_cwh);
    cudaGetSymbolAddress((void**)&cwl_p, g_cwl);
    cudaGetSymbolAddress((void**)&iwh_p, g_iwh);
    cudaGetSymbolAddress((void**)&iwl_p, g_iwl);
    cudaGetSymbolAddress((void**)&owh_p, g_owh);
    cudaGetSymbolAddress((void**)&owl_p, g_owl);
    cudaGetSymbolAddress((void**)&qkv_p, g_qkv);
    cudaGetSymbolAddress((void**)&pe_p,  g_pe);

    // 0) weight splits
    cvt_bf<<<(NIMG*DIM*KPATCH + 255)/256, 256>>>(conv_w, cwh_p, cwl_p, NIMG*DIM*KPATCH);
    cvt_bf<<<(NLAYER*3*DIM*DIM + 255)/256, 256>>>(in_w, iwh_p, iwl_p, NLAYER*3*DIM*DIM);
    cvt_bf<<<(NLAYER*DIM*DIM + 255)/256, 256>>>(out_w, owh_p, owl_p, NLAYER*DIM*DIM);

    // 1) im2col (split)
    {
        dim3 g(KPATCH/256, SEQ, NB);
        im2col_k<<<g, 256>>>(x);
    }
    // 2) patch-embed GEMM per image (+conv_b +pos) -> peh/pel
    {
        dim3 g(DIM/64, (BATCH*SEQ)/64, NIMG);
        gemm_bf3<<<g, 256>>>(imh_p, iml_p, cwh_p, cwl_p,
                             nullptr, peh_p, pel_p,
                             BATCH*SEQ, DIM, KPATCH,
                             conv_b, pos_e,
                             (long)BATCH*SEQ*KPATCH, (long)DIM*KPATCH,
                             (long)BATCH*SEQ*DIM, DIM, 0);
    }
    // 3) transformer layers
    for (int l = 0; l < NLAYER; l++) {
        {   // qkv: (peh,pel) x in_w -> g_q2 (Q pairs) + g_qkv (K/V f32), mode 1
            dim3 g((3*DIM)/64, TOK/64, 1);
            gemm_bf3<<<g, 256>>>(peh_p, pel_p,
                                 iwh_p + (long)l*3*DIM*DIM, iwl_p + (long)l*3*DIM*DIM,
                                 qkv_p, nullptr, nullptr,
                                 TOK, 3*DIM, DIM,
                                 in_b + (long)l*3*DIM, nullptr, 0, 0, 0, 0, 1);
        }
        {   // K/V transpose + convert (coalesced)
            dim3 g(NHEAD, NB);
            cvt_kv<<<g, 256>>>(qkv_p);
        }
        {
            dim3 g(SEQ/32, NB, 1);
            attn_mma<<<g, 512, ATTN_SMEM>>>(attn, l);
        }
        {   // out-proj: (oh,ol) x out_w -> pe f32 + peh/pel
            dim3 g(DIM/64, TOK/64, 1);
            gemm_bf3<<<g, 256>>>(oh_p, ol_p,
                                 owh_p + (long)l*DIM*DIM, owl_p + (long)l*DIM*DIM,
                                 pe_p, peh_p, pel_p,
                                 TOK, DIM, DIM,
                                 out_b + (long)l*DIM, nullptr, 0, 0, 0, 0, 0);
        }
    }
    // 4) sequence-mean features + MLP head
    {
        dim3 g(NIMG, BATCH);
        feat_k<<<g, DIM>>>();
    }
    head_k<<<BATCH, MLPDIM>>>(hw1, hb1, hw2, hb2, out);
}

// round 16
// speedup vs baseline: 1.0180x; 1.0180x over previous
#include <cuda_runtime.h>
#include <cuda_bf16.h>
#include <math.h>

// ---------------- problem constants ----------------
#define NIMG 4
#define BATCH 8
#define SEQ 576
#define DIM 256
#define NHEAD 8
#define DHEAD 32
#define NLAYER 6
#define MLPDIM 512
#define NB (NIMG*BATCH)      // 32
#define TOK (NB*SEQ)         // 18432
#define KPATCH 768           // 3*16*16
#define GRID24 24

// ---------------- scratch (device globals; no allocation allowed) ----------------
__device__ __nv_bfloat16 g_imh[(long)NIMG*BATCH*SEQ*KPATCH];
__device__ __nv_bfloat16 g_iml[(long)NIMG*BATCH*SEQ*KPATCH];
__device__ __nv_bfloat16 g_peh[(long)TOK*DIM];
__device__ __nv_bfloat16 g_pel[(long)TOK*DIM];
__device__ __nv_bfloat16 g_oh [(long)TOK*DIM];
__device__ __nv_bfloat16 g_ol [(long)TOK*DIM];
__device__ __nv_bfloat16 g_cwh[(long)NIMG*DIM*KPATCH];
__device__ __nv_bfloat16 g_cwl[(long)NIMG*DIM*KPATCH];
__device__ __nv_bfloat16 g_iwh[(long)NLAYER*3*DIM*DIM];
__device__ __nv_bfloat16 g_iwl[(long)NLAYER*3*DIM*DIM];
__device__ __nv_bfloat16 g_owh[(long)NLAYER*DIM*DIM];
__device__ __nv_bfloat16 g_owl[(long)NLAYER*DIM*DIM];
__device__ float g_qkv[(long)TOK*3*DIM];                 // 56.6 MB
__device__ float g_pe [(long)TOK*DIM];                   // 18.9 MB
// pre-converted attention operands (written by cvt_kv each layer)
__device__ unsigned      g_kt [(long)NB*NHEAD*32*SEQ];   // K^T tf32 [nb*h][dh][key]
__device__ __nv_bfloat16 g_vth[(long)NB*NHEAD*32*SEQ];   // V^T bf16 hi [nb*h][dh][key]
__device__ __nv_bfloat16 g_vtl[(long)NB*NHEAD*32*SEQ];   // V^T bf16 lo
__device__ float g_feat[BATCH*NIMG*DIM];

// ---------------- helpers ----------------
__device__ __forceinline__ unsigned f2tf(float f) {
    unsigned u; asm("cvt.rna.tf32.f32 %0, %1;" : "=r"(u) : "f"(f)); return u;
}
__device__ __forceinline__ void mma_tf32(float* d, const unsigned* a, unsigned b0, unsigned b1) {
    asm volatile(
        "mma.sync.aligned.m16n8k8.row.col.f32.tf32.tf32.f32 "
        "{%0,%1,%2,%3},{%4,%5,%6,%7},{%8,%9},{%0,%1,%2,%3};"
        : "+f"(d[0]), "+f"(d[1]), "+f"(d[2]), "+f"(d[3])
        : "r"(a[0]), "r"(a[1]), "r"(a[2]), "r"(a[3]), "r"(b0), "r"(b1));
}
__device__ __forceinline__ void mma_bf16(float* d, const unsigned* a, unsigned b0, unsigned b1) {
    asm volatile(
        "mma.sync.aligned.m16n8k16.row.col.f32.bf16.bf16.f32 "
        "{%0,%1,%2,%3},{%4,%5,%6,%7},{%8,%9},{%0,%1,%2,%3};"
        : "+f"(d[0]), "+f"(d[1]), "+f"(d[2]), "+f"(d[3])
        : "r"(a[0]), "r"(a[1]), "r"(a[2]), "r"(a[3]), "r"(b0), "r"(b1));
}
__device__ __forceinline__ void mma_bf16_k8(float* d, const unsigned* a, unsigned b0) {
    asm volatile(
        "mma.sync.aligned.m16n8k8.row.col.f32.bf16.bf16.f32 "
        "{%0,%1,%2,%3},{%4,%5},{%6},{%0,%1,%2,%3};"
        : "+f"(d[0]), "+f"(d[1]), "+f"(d[2]), "+f"(d[3])
        : "r"(a[0]), "r"(a[1]), "r"(b0));
}
__device__ __forceinline__ void ldsm4(unsigned* r, unsigned addr) {
    asm volatile("ldmatrix.sync.aligned.m8n8.x4.shared.b16 {%0,%1,%2,%3}, [%4];"
        : "=r"(r[0]), "=r"(r[1]), "=r"(r[2]), "=r"(r[3]) : "r"(addr));
}
__device__ __forceinline__ void cp16(void* smem, const void* g) {
    unsigned s = (unsigned)__cvta_generic_to_shared(smem);
    asm volatile("cp.async.ca.shared.global [%0], [%1], 16;\n" :: "r"(s), "l"(g));
}
__device__ __forceinline__ void splitbf(float v, __nv_bfloat16& h, __nv_bfloat16& l) {
    h = __float2bfloat16(v);
    l = __float2bfloat16(v - __bfloat162float(h));
}

// ---------------- weight split kernel ----------------
__global__ void cvt_bf(const float* __restrict__ s,
                       __nv_bfloat16* __restrict__ h, __nv_bfloat16* __restrict__ l, int n) {
    int i = blockIdx.x*256 + threadIdx.x;
    if (i >= n) return;
    splitbf(s[i], h[i], l[i]);
}

// ---------------- im2col (split bf16 planes); grid (3, SEQ, NB) ----------------
__global__ void im2col_k(const float* __restrict__ x) {
    int k  = blockIdx.x*256 + threadIdx.x;     // 0..767
    int s  = blockIdx.y;                       // 0..575
    int z  = blockIdx.z;                       // ni*BATCH + b
    int ni = z >> 3, b = z & 7;
    int c  = k >> 8;
    int py = (k >> 4) & 15;
    int px = k & 15;
    int gy = s / GRID24, gx = s - gy*GRID24;
    float v = x[(((long)b*12 + ni*3 + c)*384 + gy*16 + py)*384 + gx*16 + px];
    long idx = (((long)z*SEQ) + s)*KPATCH + k;
    splitbf(v, g_imh[idx], g_iml[idx]);
}

// ---------------- K/V transpose+convert (coalesced both sides, smem transpose) ----------------
#define CH 64
__global__ __launch_bounds__(256) void cvt_kv(const float* __restrict__ qkv) {
    int h = blockIdx.x, nb = blockIdx.y;
    __shared__ __align__(16) unsigned       sk [32][CH+4];
    __shared__ __align__(16) unsigned short svh[32][CH+8];
    __shared__ __align__(16) unsigned short svl[32][CH+8];
    const int t = threadIdx.x;
    const int lane = t & 31, wrp = t >> 5;
    const long base  = ((long)nb*SEQ)*768 + 256 + h*32 + lane;
    const long obase = (long)(nb*NHEAD + h)*32;
    const int dh = t >> 3, c8 = (t & 7)*8;

    for (int kb = 0; kb < SEQ; kb += CH) {
        #pragma unroll
        for (int i = 0; i < 8; i++) {
            int kc = wrp + i*8;
            long rp = base + (long)(kb + kc)*768;
            float kv = qkv[rp];
            float vv = qkv[rp + 256];
            sk[lane][kc] = f2tf(kv);
            __nv_bfloat16 hh, ll; splitbf(vv, hh, ll);
            svh[lane][kc] = *(unsigned short*)&hh;
            svl[lane][kc] = *(unsigned short*)&ll;
        }
        __syncthreads();
        {
            unsigned* dst = g_kt + (obase + dh)*SEQ + kb + c8;
            *(uint4*)dst       = *(const uint4*)&sk[dh][c8];
            *(uint4*)(dst + 4) = *(const uint4*)&sk[dh][c8 + 4];
            *(uint4*)(g_vth + (obase + dh)*SEQ + kb + c8) = *(const uint4*)&svh[dh][c8];
            *(uint4*)(g_vtl + (obase + dh)*SEQ + kb + c8) = *(const uint4*)&svl[dh][c8];
        }
        __syncthreads();
    }
}

// ---------------- bf16x3 tensor GEMM (R13-validated): ldmatrix + reg double-buffer ----------------
#define BSTR 40
__global__ __launch_bounds__(256) void gemm_bf3(
    const __nv_bfloat16* __restrict__ Ah, const __nv_bfloat16* __restrict__ Al,
    const __nv_bfloat16* __restrict__ Bh, const __nv_bfloat16* __restrict__ Bl,
    float* __restrict__ Cf, __nv_bfloat16* __restrict__ Ch, __nv_bfloat16* __restrict__ Cl,
    int M, int N, int K,
    const float* __restrict__ bias, const float* __restrict__ pos,
    long strideA, long strideB, long strideC, int strideBias)
{
    Ah += (long)blockIdx.z * strideA;  Al += (long)blockIdx.z * strideA;
    Bh += (long)blockIdx.z * strideB;  Bl += (long)blockIdx.z * strideB;
    if (Cf) Cf += (long)blockIdx.z * strideC;
    if (Ch) { Ch += (long)blockIdx.z * strideC; Cl += (long)blockIdx.z * strideC; }
    if (bias) bias += (long)blockIdx.z * strideBias;

    __shared__ __nv_bfloat16 sAh[64][BSTR], sAl[64][BSTR];
    __shared__ __nv_bfloat16 sBh[64][BSTR], sBl[64][BSTR];

    const int tid  = threadIdx.x;
    const int lane = tid & 31;
    const int w    = tid >> 5;
    const int r4   = lane >> 2;
    const int c4   = lane & 3;
    const int wm   = w & 3, wn = w >> 2;
    const int m0   = blockIdx.y * 64, n0 = blockIdx.x * 64;
    const int lrow = tid >> 2;
    const int lk8  = (tid & 3) * 8;

    const int a_row = wm*16 + (lane & 15);
    const int a_col = (lane >> 4) * 8;
    const unsigned aAh = (unsigned)__cvta_generic_to_shared(&sAh[a_row][a_col]);
    const unsigned aAl = (unsigned)__cvta_generic_to_shared(&sAl[a_row][a_col]);
    const int b_rb = wn*32 + (lane & 7) + ((lane >> 4) << 3);
    const int b_cb = ((lane >> 3) & 1) * 8;
    const unsigned bBh0 = (unsigned)__cvta_generic_to_shared(&sBh[b_rb][b_cb]);
    const unsigned bBl0 = (unsigned)__cvta_generic_to_shared(&sBl[b_rb][b_cb]);
    const unsigned tstep = 16*BSTR*2;

    const __nv_bfloat16* pAh = &Ah[(long)(m0 + lrow)*K + lk8];
    const __nv_bfloat16* pAl = &Al[(long)(m0 + lrow)*K + lk8];
    const __nv_bfloat16* pBh = &Bh[(long)(n0 + lrow)*K + lk8];
    const __nv_bfloat16* pBl = &Bl[(long)(n0 + lrow)*K + lk8];

    float acc[4][4] = {};
    uint4 rah = *(const uint4*)&pAh[0], ral = *(const uint4*)&pAl[0];
    uint4 rbh = *(const uint4*)&pBh[0], rbl = *(const uint4*)&pBl[0];

    for (int k0 = 0; k0 < K; k0 += 32) {
        *(uint4*)&sAh[lrow][lk8] = rah; *(uint4*)&sAl[lrow][lk8] = ral;
        *(uint4*)&sBh[lrow][lk8] = rbh; *(uint4*)&sBl[lrow][lk8] = rbl;
        __syncthreads();
        if (k0 + 32 < K) {
            rah = *(const uint4*)&pAh[k0+32]; ral = *(const uint4*)&pAl[k0+32];
            rbh = *(const uint4*)&pBh[k0+32]; rbl = *(const uint4*)&pBl[k0+32];
        }
        #pragma unroll
        for (int kk = 0; kk < 2; kk++) {
            const unsigned koff = kk*32;
            unsigned ah[4], al[4];
            ldsm4(ah, aAh + koff);
            ldsm4(al, aAl + koff);
            #pragma unroll
            for (int t = 0; t < 2; t++) {
                unsigned bh[4], bl[4];
                ldsm4(bh, bBh0 + t*tstep + koff);
                ldsm4(bl, bBl0 + t*tstep + koff);
                mma_bf16(acc[2*t],   ah, bh[0], bh[1]);
                mma_bf16(acc[2*t],   al, bh[0], bh[1]);
                mma_bf16(acc[2*t],   ah, bl[0], bl[1]);
                mma_bf16(acc[2*t+1], ah, bh[2], bh[3]);
                mma_bf16(acc[2*t+1], al, bh[2], bh[3]);
                mma_bf16(acc[2*t+1], ah, bl[2], bl[3]);
            }
        }
        __syncthreads();
    }

    #pragma unroll
    for (int nt = 0; nt < 4; nt++) {
        int n = n0 + wn*32 + nt*8 + c4*2;
        float bx = 0.f, by = 0.f;
        if (bias) { bx = bias[n]; by = bias[n+1]; }
        int row0 = m0 + wm*16 + r4, row1 = row0 + 8;
        float v00 = acc[nt][0]+bx, v01 = acc[nt][1]+by;
        float v10 = acc[nt][2]+bx, v11 = acc[nt][3]+by;
        if (pos) {
            const float* p0 = pos + (long)(row0 % SEQ)*DIM + n;
            const float* p1 = pos + (long)(row1 % SEQ)*DIM + n;
            v00 += p0[0]; v01 += p0[1]; v10 += p1[0]; v11 += p1[1];
        }
        if (Cf) {
            *(float2*)&Cf[(long)row0*N + n] = make_float2(v00, v01);
            *(float2*)&Cf[(long)row1*N + n] = make_float2(v10, v11);
        }
        if (Ch) {
            __nv_bfloat162 h0, l0, h1, l1;
            splitbf(v00, h0.x, l0.x); splitbf(v01, h0.y, l0.y);
            splitbf(v10, h1.x, l1.x); splitbf(v11, h1.y, l1.y);
            *(__nv_bfloat162*)&Ch[(long)row0*N + n] = h0;
            *(__nv_bfloat162*)&Cl[(long)row0*N + n] = l0;
            *(__nv_bfloat162*)&Ch[(long)row1*N + n] = h1;
            *(__nv_bfloat162*)&Cl[(long)row1*N + n] = l1;
        }
    }
}

// ---------------- fused attention: split-group cp.async P1 + ldmatrix PV ----------------
#define KSTRD 580
#define VSTR  292
#define ATTN_FLOATS (32*KSTRD + 2*32*VSTR + 256 + 32 + 32)
#define ATTN_SMEM (ATTN_FLOATS*4)   // 150,272 B

__global__ __launch_bounds__(512, 1) void attn_mma(
    const float* __restrict__ qkv, float* __restrict__ attn_out, int layer)
{
    extern __shared__ float sm[];
    unsigned* Kt   = (unsigned*)sm;                  // [32 dh][580] tf32 K^T; buf overlay
    unsigned* Vh   = Kt + 32*KSTRD;                  // [32 dh][292] bf16-pair V^T hi
    unsigned* Vl   = Vh + 32*VSTR;                   // [32 dh][292] bf16-pair V^T lo
    float* pbufA   = sm + 32*KSTRD + 2*32*VSTR;      // [32][8]
    float* rowmax  = pbufA + 256;                    // [32]
    float* rinv    = rowmax + 32;                    // [32]
    float* buf     = (float*)Kt;                     // PV partial-O scratch (32 KB)

    const int tid  = threadIdx.x;
    const int lane = tid & 31;
    const int w    = tid >> 5;                  // 0..15
    const int r4   = lane >> 2;
    const int c4   = lane & 3;
    const int ws   = w >> 3;                    // q-subtile (16 q)
    const int wk   = w & 7;                     // key-slice (72 keys)
    const int qt   = blockIdx.x;                // 0..17
    const int nb   = blockIdx.y;                // 0..31
    const float* qbase = qkv + (long)nb*SEQ*768;
    const float SC = 0.17677669529663687f;      // 1/sqrt(32)

    // P1 copy assignments
    const int kdh = tid >> 4, kci = tid & 15;
    const int vp  = tid >> 8, vrem = tid & 255;
    const int vdh = vrem >> 3, vci = vrem & 7;
    // PV ldmatrix base
    const unsigned vb_h = (unsigned)__cvta_generic_to_shared(&Vh[lane*VSTR + wk*36]);
    const unsigned vb_l = (unsigned)__cvta_generic_to_shared(&Vl[lane*VSTR + wk*36]);

    float am[9][4];
    #pragma unroll
    for (int nt = 0; nt < 9; nt++)
        #pragma unroll
        for (int i = 0; i < 4; i++) am[nt][i] = 0.f;

    for (int h = 0; h < NHEAD; h++) {
        // ---- P1: cp.async, K in group 0, V in group 1; wait only K before P2 ----
        {
            const long kvb = (long)(nb*NHEAD + h)*32;
            const unsigned* gK = g_kt + (kvb + kdh)*SEQ;
            unsigned* dK = Kt + kdh*KSTRD;
            #pragma unroll
            for (int j = 0; j < 9; j++) {
                int c4i = (kci + j*16)*4;
                cp16(&dK[c4i], &gK[c4i]);
            }
            asm volatile("cp.async.commit_group;\n");   // group: K
            const __nv_bfloat16* gV = (vp ? g_vtl : g_vth) + (kvb + vdh)*SEQ;
            unsigned* dV = (vp ? Vl : Vh) + vdh*VSTR;
            #pragma unroll
            for (int j = 0; j < 9; j++) {
                int cc = vci + j*8;
                cp16(&dV[cc*4], &gV[cc*8]);
            }
            asm volatile("cp.async.commit_group;\n");   // group: V
            asm volatile("cp.async.wait_group 1;\n");   // K complete; V in flight
        }
        __syncthreads();                        // S1

        // ---- P2: S = Q K^T (Q hi/lo tf32 split); warp (ws,wk) -> 16q x 72k ----
        float acc[9][4];
        #pragma unroll
        for (int nt = 0; nt < 9; nt++)
            #pragma unroll
            for (int i = 0; i < 4; i++) acc[nt][i] = 0.f;

        #pragma unroll
        for (int kc = 0; kc < 4; kc++) {
            unsigned ah[4], al[4];
            {
                const float* qp = qbase + (long)(qt*32 + ws*16 + r4)*768 + h*32 + kc*8 + c4;
                float q0 = qp[0]*SC, q1 = qp[8*768]*SC, q2 = qp[4]*SC, q3 = qp[8*768+4]*SC;
                ah[0]=f2tf(q0); al[0]=f2tf(q0-__uint_as_float(ah[0]));
                ah[1]=f2tf(q1); al[1]=f2tf(q1-__uint_as_float(ah[1]));
                ah[2]=f2tf(q2); al[2]=f2tf(q2-__uint_as_float(ah[2]));
                ah[3]=f2tf(q3); al[3]=f2tf(q3-__uint_as_float(ah[3]));
            }
            const unsigned* kb  = &Kt[(kc*8 + c4)*KSTRD + wk*72 + r4];
            const unsigned* kb4 = kb + 4*KSTRD;
            #pragma unroll
            for (int nt = 0; nt < 9; nt++) {
                unsigned b0 = kb[nt*8], b1 = kb4[nt*8];
                mma_tf32(acc[nt], ah, b0, b1);
                mma_tf32(acc[nt], al, b0, b1);
            }
        }
        // partial row max
        {
            float pm[2] = {-1e30f, -1e30f};
            #pragma unroll
            for (int nt = 0; nt < 9; nt++) {
                pm[0] = fmaxf(pm[0], fmaxf(acc[nt][0], acc[nt][1]));
                pm[1] = fmaxf(pm[1], fmaxf(acc[nt][2], acc[nt][3]));
            }
            #pragma unroll
            for (int s = 0; s < 2; s++) {
                pm[s] = fmaxf(pm[s], __shfl_xor_sync(0xffffffffu, pm[s], 1));
                pm[s] = fmaxf(pm[s], __shfl_xor_sync(0xffffffffu, pm[s], 2));
            }
            if (c4 == 0) {
                pbufA[(ws*16 + r4)*8 + wk]     = pm[0];
                pbufA[(ws*16 + 8 + r4)*8 + wk] = pm[1];
            }
        }
        __syncthreads();                        // S2
        if (tid < 32) {
            float m = pbufA[tid*8];
            #pragma unroll
            for (int i = 1; i < 8; i++) m = fmaxf(m, pbufA[tid*8 + i]);
            rowmax[tid] = m;
        }
        __syncthreads();                        // S3
        // ---- P4: e = exp(s - rowmax) in registers; row sums ----
        {
            float rm0 = rowmax[ws*16 + r4], rm1 = rowmax[ws*16 + 8 + r4];
            float ps[2] = {0.f, 0.f};
            #pragma unroll
            for (int nt = 0; nt < 9; nt++) {
                float e0 = __expf(acc[nt][0] - rm0);
                float e1 = __expf(acc[nt][1] - rm0);
                float e2 = __expf(acc[nt][2] - rm1);
                float e3 = __expf(acc[nt][3] - rm1);
                acc[nt][0] = e0; acc[nt][1] = e1;
                acc[nt][2] = e2; acc[nt][3] = e3;
                ps[0] += e0 + e1;
                ps[1] += e2 + e3;
            }
            #pragma unroll
            for (int s = 0; s < 2; s++) {
                ps[s] += __shfl_xor_sync(0xffffffffu, ps[s], 1);
                ps[s] += __shfl_xor_sync(0xffffffffu, ps[s], 2);
            }
            if (c4 == 0) {
                pbufA[(ws*16 + r4)*8 + wk]     = ps[0];
                pbufA[(ws*16 + 8 + r4)*8 + wk] = ps[1];
            }
        }
        __syncthreads();                        // S4
        if (tid < 32) {
            float sa = 0.f;
            #pragma unroll
            for (int i = 0; i < 8; i++) sa += pbufA[tid*8 + i];
            rinv[tid] = __frcp_rn(sa);
        }
        // V must be resident before PV; each thread drains its own groups,
        // then S5 publishes across the CTA.
        asm volatile("cp.async.wait_group 0;\n");
        __syncthreads();                        // S5
        // ---- P5: Am += e * rinv / 8 (registers) ----
        {
            float ra0 = rinv[ws*16 + r4]*0.125f, ra1 = rinv[ws*16 + 8 + r4]*0.125f;
            #pragma unroll
            for (int nt = 0; nt < 9; nt++) {
                am[nt][0] += acc[nt][0] * ra0;
                am[nt][1] += acc[nt][1] * ra0;
                am[nt][2] += acc[nt][2] * ra1;
                am[nt][3] += acc[nt][3] * ra1;
            }
        }
        // ---- pack E into bf16 hi/lo fragments ----
        unsigned eh[9][2], el[9][2];
        #pragma unroll
        for (int nt = 0; nt < 9; nt++) {
            __nv_bfloat162 h01 = __floats2bfloat162_rn(acc[nt][0], acc[nt][1]);
            __nv_bfloat162 h23 = __floats2bfloat162_rn(acc[nt][2], acc[nt][3]);
            __nv_bfloat162 l01 = __floats2bfloat162_rn(acc[nt][0] - __bfloat162float(h01.x),
                                                       acc[nt][1] - __bfloat162float(h01.y));
            __nv_bfloat162 l23 = __floats2bfloat162_rn(acc[nt][2] - __bfloat162float(h23.x),
                                                       acc[nt][3] - __bfloat162float(h23.y));
            eh[nt][0] = *(unsigned*)&h01; eh[nt][1] = *(unsigned*)&h23;
            el[nt][0] = *(unsigned*)&l01; el[nt][1] = *(unsigned*)&l23;
        }
        // ---- PV via ldmatrix: partial O[16q x 32dh] over this warp's 72 keys ----
        float po[4][4] = {};
        #pragma unroll
        for (int s = 0; s < 4; s++) {
            unsigned a_h[4] = {eh[2*s][0], eh[2*s][1], eh[2*s+1][0], eh[2*s+1][1]};
            unsigned a_l[4] = {el[2*s][0], el[2*s][1], el[2*s+1][0], el[2*s+1][1]};
            unsigned bh0[4], bh1[4], bl0[4], bl1[4];
            ldsm4(bh0, vb_h + s*32);
            ldsm4(bh1, vb_h + s*32 + 16);
            ldsm4(bl0, vb_l + s*32);
            ldsm4(bl1, vb_l + s*32 + 16);
            #pragma unroll
            for (int nt6 = 0; nt6 < 4; nt6++) {
                mma_bf16(po[nt6], a_h, bh0[nt6], bh1[nt6]);
                mma_bf16(po[nt6], a_l, bh0[nt6], bh1[nt6]);
                mma_bf16(po[nt6], a_h, bl0[nt6], bl1[nt6]);
            }
        }
        {   // tail keys 64..71 (k8)
            unsigned bh0[4], bl0[4];
            ldsm4(bh0, vb_h + 128);
            ldsm4(bl0, vb_l + 128);
            #pragma unroll
            for (int nt6 = 0; nt6 < 4; nt6++) {
                mma_bf16_k8(po[nt6], eh[8], bh0[nt6]);
                mma_bf16_k8(po[nt6], el[8], bh0[nt6]);
                mma_bf16_k8(po[nt6], eh[8], bl0[nt6]);
            }
        }
        // ---- store partials into buf (K region; all K reads done since S2) ----
        #pragma unroll
        for (int nt6 = 0; nt6 < 4; nt6++)
            *(float4*)&buf[(((ws*4 + nt6)*8 + wk)*32 + lane)*4] =
                make_float4(po[nt6][0], po[nt6][1], po[nt6][2], po[nt6][3]);
        __syncthreads();                        // S6
        // ---- reduce 8 key-slices; scale; write split bf16 O ----
        if (w < 8) {
            int rws = w >> 2, rnt = w & 3;
            float4 s4 = make_float4(0.f, 0.f, 0.f, 0.f);
            #pragma unroll
            for (int k = 0; k < 8; k++) {
                float4 p = *(const float4*)&buf[(((rws*4 + rnt)*8 + k)*32 + lane)*4];
                s4.x += p.x; s4.y += p.y; s4.z += p.z; s4.w += p.w;
            }
            int q0 = rws*16 + r4;
            int dh = rnt*8 + c4*2;
            float ri0 = rinv[q0], ri1 = rinv[q0 + 8];
            float x0 = s4.x*ri0, x1 = s4.y*ri0;
            float x2 = s4.z*ri1, x3 = s4.w*ri1;
            long orow = (long)(nb*SEQ + qt*32 + q0)*DIM + h*32 + dh;
            __nv_bfloat162 h0, l0, h1, l1;
            splitbf(x0, h0.x, l0.x); splitbf(x1, h0.y, l0.y);
            splitbf(x2, h1.x, l1.x); splitbf(x3, h1.y, l1.y);
            *(__nv_bfloat162*)&g_oh[orow]         = h0;
            *(__nv_bfloat162*)&g_ol[orow]         = l0;
            *(__nv_bfloat162*)&g_oh[orow + 8*DIM] = h1;
            *(__nv_bfloat162*)&g_ol[orow + 8*DIM] = l1;
        }
        __syncthreads();                        // S7: buf reads done before next P1
    }
    // ---- final: head-mean attention from registers ----
    float* aout = attn_out + (long)(layer*NB + nb)*SEQ*SEQ + (long)qt*32*SEQ;
    #pragma unroll
    for (int nt = 0; nt < 9; nt++) {
        int col = wk*72 + nt*8 + c4*2;
        *(float2*)&aout[(long)(ws*16 + r4)*SEQ + col]     = make_float2(am[nt][0], am[nt][1]);
        *(float2*)&aout[(long)(ws*16 + 8 + r4)*SEQ + col] = make_float2(am[nt][2], am[nt][3]);
    }
}

// ---------------- feature mean over sequence ----------------
__global__ void feat_k(void) {
    int ni = blockIdx.x, b = blockIdx.y, d = threadIdx.x;
    const float* p = g_pe + ((long)(ni*BATCH + b)*SEQ)*DIM + d;
    float s = 0.f;
    for (int t = 0; t < SEQ; t++) s += p[(long)t*DIM];
    g_feat[b*(NIMG*DIM) + ni*DIM + d] = s * (1.0f/576.0f);
}

// ---------------- MLP head ----------------
__global__ void head_k(const float* __restrict__ w1, const float* __restrict__ b1,
                       const float* __restrict__ w2, const float* __restrict__ b2,
                       float* __restrict__ out) {
    __shared__ float fs[NIMG*DIM];
    __shared__ float hs[MLPDIM];
    int b = blockIdx.x, tid = threadIdx.x;
    for (int t = tid; t < NIMG*DIM; t += MLPDIM) fs[t] = g_feat[b*NIMG*DIM + t];
    __syncthreads();
    float a = b1[tid];
    const float* wr = w1 + (long)tid*(NIMG*DIM);
    for (int d2 = 0; d2 < NIMG*DIM; d2++) a += fs[d2]*wr[d2];
    hs[tid] = fmaxf(a, 0.f) * w2[tid];
    __syncthreads();
    for (int st = 256; st > 0; st >>= 1) {
        if (tid < st) hs[tid] += hs[tid + st];
        __syncthreads();
    }
    if (tid == 0) out[b] = hs[0] + b2[0];
}

// ---------------- launch ----------------
extern "C" void kernel_launch(void* const* d_in, const int* in_sizes, int n_in,
                              void* d_out, int out_size) {
    const float* x      = (const float*)d_in[0];
    const float* conv_w = (const float*)d_in[1];
    const float* conv_b = (const float*)d_in[2];
    const float* pos_e  = (const float*)d_in[3];
    const float* in_w   = (const float*)d_in[4];
    const float* in_b   = (const float*)d_in[5];
    const float* out_w  = (const float*)d_in[6];
    const float* out_b  = (const float*)d_in[7];
    const float* hw1    = (const float*)d_in[8];
    const float* hb1    = (const float*)d_in[9];
    const float* hw2    = (const float*)d_in[10];
    const float* hb2    = (const float*)d_in[11];

    float* out  = (float*)d_out;            // [8]
    float* attn = out + BATCH;              // [6,4,8,576,576]

    cudaFuncSetAttribute(attn_mma, cudaFuncAttributeMaxDynamicSharedMemorySize, ATTN_SMEM);

    __nv_bfloat16 *imh_p, *iml_p, *peh_p, *pel_p, *oh_p, *ol_p;
    __nv_bfloat16 *cwh_p, *cwl_p, *iwh_p, *iwl_p, *owh_p, *owl_p;
    float *qkv_p, *pe_p;
    cudaGetSymbolAddress((void**)&imh_p, g_imh);
    cudaGetSymbolAddress((void**)&iml_p, g_iml);
    cudaGetSymbolAddress((void**)&peh_p, g_peh);
    cudaGetSymbolAddress((void**)&pel_p, g_pel);
    cudaGetSymbolAddress((void**)&oh_p,  g_oh);
    cudaGetSymbolAddress((void**)&ol_p,  g_ol);
    cudaGetSymbolAddress((void**)&cwh_p, g_cwh);
    cudaGetSymbolAddress((void**)&cwl_p, g_cwl);
    cudaGetSymbolAddress((void**)&iwh_p, g_iwh);
    cudaGetSymbolAddress((void**)&iwl_p, g_iwl);
    cudaGetSymbolAddress((void**)&owh_p, g_owh);
    cudaGetSymbolAddress((void**)&owl_p, g_owl);
    cudaGetSymbolAddress((void**)&qkv_p, g_qkv);
    cudaGetSymbolAddress((void**)&pe_p,  g_pe);

    // 0) weight splits
    cvt_bf<<<(NIMG*DIM*KPATCH + 255)/256, 256>>>(conv_w, cwh_p, cwl_p, NIMG*DIM*KPATCH);
    cvt_bf<<<(NLAYER*3*DIM*DIM + 255)/256, 256>>>(in_w, iwh_p, iwl_p, NLAYER*3*DIM*DIM);
    cvt_bf<<<(NLAYER*DIM*DIM + 255)/256, 256>>>(out_w, owh_p, owl_p, NLAYER*DIM*DIM);

    // 1) im2col (split)
    {
        dim3 g(KPATCH/256, SEQ, NB);
        im2col_k<<<g, 256>>>(x);
    }
    // 2) patch-embed GEMM per image (+conv_b +pos) -> peh/pel
    {
        dim3 g(DIM/64, (BATCH*SEQ)/64, NIMG);
        gemm_bf3<<<g, 256>>>(imh_p, iml_p, cwh_p, cwl_p,
                             nullptr, peh_p, pel_p,
                             BATCH*SEQ, DIM, KPATCH,
                             conv_b, pos_e,
                             (long)BATCH*SEQ*KPATCH, (long)DIM*KPATCH,
                             (long)BATCH*SEQ*DIM, DIM);
    }
    // 3) transformer layers
    for (int l = 0; l < NLAYER; l++) {
        {   // qkv: (peh,pel) x in_w -> f32 qkv
            dim3 g((3*DIM)/64, TOK/64, 1);
            gemm_bf3<<<g, 256>>>(peh_p, pel_p,
                                 iwh_p + (long)l*3*DIM*DIM, iwl_p + (long)l*3*DIM*DIM,
                                 qkv_p, nullptr, nullptr,
                                 TOK, 3*DIM, DIM,
                                 in_b + (long)l*3*DIM, nullptr, 0, 0, 0, 0);
        }
        {   // K/V transpose + convert (coalesced)
            dim3 g(NHEAD, NB);
            cvt_kv<<<g, 256>>>(qkv_p);
        }
        {
            dim3 g(SEQ/32, NB, 1);
            attn_mma<<<g, 512, ATTN_SMEM>>>(qkv_p, attn, l);
        }
        {   // out-proj: (oh,ol) x out_w -> pe f32 + peh/pel
            dim3 g(DIM/64, TOK/64, 1);
            gemm_bf3<<<g, 256>>>(oh_p, ol_p,
                                 owh_p + (long)l*DIM*DIM, owl_p + (long)l*DIM*DIM,
                                 pe_p, peh_p, pel_p,
                                 TOK, DIM, DIM,
                                 out_b + (long)l*DIM, nullptr, 0, 0, 0, 0);
        }
    }
    // 4) sequence-mean features + MLP head
    {
        dim3 g(NIMG, BATCH);
        feat_k<<<g, DIM>>>();
    }
    head_k<<<BATCH, MLPDIM>>>(hw1, hb1, hw2, hb2, out);
}

// round 17
// speedup vs baseline: 1.1226x; 1.1027x over previous
#include <cuda_runtime.h>
#include <cuda_bf16.h>
#include <math.h>

// ---------------- problem constants ----------------
#define NIMG 4
#define BATCH 8
#define SEQ 576
#define DIM 256
#define NHEAD 8
#define DHEAD 32
#define NLAYER 6
#define MLPDIM 512
#define NB (NIMG*BATCH)      // 32
#define TOK (NB*SEQ)         // 18432
#define KPATCH 768           // 3*16*16
#define GRID24 24

// ---------------- scratch (device globals; no allocation allowed) ----------------
__device__ __nv_bfloat16 g_imh[(long)NIMG*BATCH*SEQ*KPATCH];
__device__ __nv_bfloat16 g_iml[(long)NIMG*BATCH*SEQ*KPATCH];
__device__ __nv_bfloat16 g_peh[(long)TOK*DIM];
__device__ __nv_bfloat16 g_pel[(long)TOK*DIM];
__device__ __nv_bfloat16 g_oh [(long)TOK*DIM];
__device__ __nv_bfloat16 g_ol [(long)TOK*DIM];
__device__ __nv_bfloat16 g_cwh[(long)NIMG*DIM*KPATCH];
__device__ __nv_bfloat16 g_cwl[(long)NIMG*DIM*KPATCH];
__device__ __nv_bfloat16 g_iwh[(long)NLAYER*3*DIM*DIM];
__device__ __nv_bfloat16 g_iwl[(long)NLAYER*3*DIM*DIM];
__device__ __nv_bfloat16 g_owh[(long)NLAYER*DIM*DIM];
__device__ __nv_bfloat16 g_owl[(long)NLAYER*DIM*DIM];
__device__ float g_qkv[(long)TOK*3*DIM];                 // 56.6 MB
__device__ float g_pe [(long)TOK*DIM];                   // 18.9 MB
// pre-converted attention operands (written by cvt_kv each layer)
__device__ __nv_bfloat16 g_kbh[(long)NB*NHEAD*SEQ*32];   // K bf16 hi [nb*h][key][dh]
__device__ __nv_bfloat16 g_kbl[(long)NB*NHEAD*SEQ*32];   // K bf16 lo
__device__ __nv_bfloat16 g_vth[(long)NB*NHEAD*32*SEQ];   // V^T bf16 hi [nb*h][dh][key]
__device__ __nv_bfloat16 g_vtl[(long)NB*NHEAD*32*SEQ];   // V^T bf16 lo
__device__ float g_feat[BATCH*NIMG*DIM];

// ---------------- helpers ----------------
__device__ __forceinline__ unsigned f2tf(float f) {
    unsigned u; asm("cvt.rna.tf32.f32 %0, %1;" : "=r"(u) : "f"(f)); return u;
}
__device__ __forceinline__ void mma_bf16(float* d, const unsigned* a, unsigned b0, unsigned b1) {
    asm volatile(
        "mma.sync.aligned.m16n8k16.row.col.f32.bf16.bf16.f32 "
        "{%0,%1,%2,%3},{%4,%5,%6,%7},{%8,%9},{%0,%1,%2,%3};"
        : "+f"(d[0]), "+f"(d[1]), "+f"(d[2]), "+f"(d[3])
        : "r"(a[0]), "r"(a[1]), "r"(a[2]), "r"(a[3]), "r"(b0), "r"(b1));
}
__device__ __forceinline__ void mma_bf16_k8(float* d, const unsigned* a, unsigned b0) {
    asm volatile(
        "mma.sync.aligned.m16n8k8.row.col.f32.bf16.bf16.f32 "
        "{%0,%1,%2,%3},{%4,%5},{%6},{%0,%1,%2,%3};"
        : "+f"(d[0]), "+f"(d[1]), "+f"(d[2]), "+f"(d[3])
        : "r"(a[0]), "r"(a[1]), "r"(b0));
}
__device__ __forceinline__ void ldsm4(unsigned* r, unsigned addr) {
    asm volatile("ldmatrix.sync.aligned.m8n8.x4.shared.b16 {%0,%1,%2,%3}, [%4];"
        : "=r"(r[0]), "=r"(r[1]), "=r"(r[2]), "=r"(r[3]) : "r"(addr));
}
__device__ __forceinline__ void ldsm2(unsigned* r, unsigned addr) {
    asm volatile("ldmatrix.sync.aligned.m8n8.x2.shared.b16 {%0,%1}, [%2];"
        : "=r"(r[0]), "=r"(r[1]) : "r"(addr));
}
__device__ __forceinline__ void cp16(void* smem, const void* g) {
    unsigned s = (unsigned)__cvta_generic_to_shared(smem);
    asm volatile("cp.async.ca.shared.global [%0], [%1], 16;\n" :: "r"(s), "l"(g));
}
__device__ __forceinline__ void splitbf(float v, __nv_bfloat16& h, __nv_bfloat16& l) {
    h = __float2bfloat16(v);
    l = __float2bfloat16(v - __bfloat162float(h));
}

// ---------------- weight split kernel ----------------
__global__ void cvt_bf(const float* __restrict__ s,
                       __nv_bfloat16* __restrict__ h, __nv_bfloat16* __restrict__ l, int n) {
    int i = blockIdx.x*256 + threadIdx.x;
    if (i >= n) return;
    splitbf(s[i], h[i], l[i]);
}

// ---------------- im2col (split bf16 planes); grid (3, SEQ, NB) ----------------
__global__ void im2col_k(const float* __restrict__ x) {
    int k  = blockIdx.x*256 + threadIdx.x;     // 0..767
    int s  = blockIdx.y;                       // 0..575
    int z  = blockIdx.z;                       // ni*BATCH + b
    int ni = z >> 3, b = z & 7;
    int c  = k >> 8;
    int py = (k >> 4) & 15;
    int px = k & 15;
    int gy = s / GRID24, gx = s - gy*GRID24;
    float v = x[(((long)b*12 + ni*3 + c)*384 + gy*16 + py)*384 + gx*16 + px];
    long idx = (((long)z*SEQ) + s)*KPATCH + k;
    splitbf(v, g_imh[idx], g_iml[idx]);
}

// ---------------- K/V convert: K direct (no transpose), V smem transpose ----------------
#define CH 64
__global__ __launch_bounds__(256) void cvt_kv(const float* __restrict__ qkv) {
    int h = blockIdx.x, nb = blockIdx.y;
    __shared__ __align__(16) unsigned short svh[32][CH+8];
    __shared__ __align__(16) unsigned short svl[32][CH+8];
    const int t = threadIdx.x;
    const int lane = t & 31, wrp = t >> 5;
    const long inb   = ((long)nb*SEQ)*768 + 256 + h*32;
    const long kout  = (long)(nb*NHEAD + h)*SEQ*32;
    const long vout  = (long)(nb*NHEAD + h)*32*SEQ;
    const int dh = t >> 3, c8 = (t & 7)*8;

    // ---- K: bf16 hi/lo, natural [key][dh] layout, fully coalesced ----
    {
        int key0 = t >> 4, d2 = (t & 15)*2;    // 16 keys per pass, 2 dh each
        for (int kb = 0; kb < SEQ; kb += 16) {
            int key = kb + key0;
            float2 v = *(const float2*)&qkv[inb + (long)key*768 + d2];
            __nv_bfloat162 hh, ll;
            splitbf(v.x, hh.x, ll.x); splitbf(v.y, hh.y, ll.y);
            *(__nv_bfloat162*)&g_kbh[kout + key*32 + d2] = hh;
            *(__nv_bfloat162*)&g_kbl[kout + key*32 + d2] = ll;
        }
    }
    // ---- V: transpose via smem ----
    const long vbase = inb + 256 + lane;       // V region, dh = lane
    for (int kb = 0; kb < SEQ; kb += CH) {
        #pragma unroll
        for (int i = 0; i < 8; i++) {
            int kc = wrp + i*8;
            float vv = qkv[vbase + (long)(kb + kc)*768];
            __nv_bfloat16 hh, ll; splitbf(vv, hh, ll);
            svh[lane][kc] = *(unsigned short*)&hh;
            svl[lane][kc] = *(unsigned short*)&ll;
        }
        __syncthreads();
        *(uint4*)&g_vth[vout + (long)dh*SEQ + kb + c8] = *(const uint4*)&svh[dh][c8];
        *(uint4*)&g_vtl[vout + (long)dh*SEQ + kb + c8] = *(const uint4*)&svl[dh][c8];
        __syncthreads();
    }
}

// ---------------- bf16x3 tensor GEMM (R13-validated): ldmatrix + reg double-buffer ----------------
#define BSTR 40
__global__ __launch_bounds__(256) void gemm_bf3(
    const __nv_bfloat16* __restrict__ Ah, const __nv_bfloat16* __restrict__ Al,
    const __nv_bfloat16* __restrict__ Bh, const __nv_bfloat16* __restrict__ Bl,
    float* __restrict__ Cf, __nv_bfloat16* __restrict__ Ch, __nv_bfloat16* __restrict__ Cl,
    int M, int N, int K,
    const float* __restrict__ bias, const float* __restrict__ pos,
    long strideA, long strideB, long strideC, int strideBias)
{
    Ah += (long)blockIdx.z * strideA;  Al += (long)blockIdx.z * strideA;
    Bh += (long)blockIdx.z * strideB;  Bl += (long)blockIdx.z * strideB;
    if (Cf) Cf += (long)blockIdx.z * strideC;
    if (Ch) { Ch += (long)blockIdx.z * strideC; Cl += (long)blockIdx.z * strideC; }
    if (bias) bias += (long)blockIdx.z * strideBias;

    __shared__ __nv_bfloat16 sAh[64][BSTR], sAl[64][BSTR];
    __shared__ __nv_bfloat16 sBh[64][BSTR], sBl[64][BSTR];

    const int tid  = threadIdx.x;
    const int lane = tid & 31;
    const int w    = tid >> 5;
    const int r4   = lane >> 2;
    const int c4   = lane & 3;
    const int wm   = w & 3, wn = w >> 2;
    const int m0   = blockIdx.y * 64, n0 = blockIdx.x * 64;
    const int lrow = tid >> 2;
    const int lk8  = (tid & 3) * 8;

    const int a_row = wm*16 + (lane & 15);
    const int a_col = (lane >> 4) * 8;
    const unsigned aAh = (unsigned)__cvta_generic_to_shared(&sAh[a_row][a_col]);
    const unsigned aAl = (unsigned)__cvta_generic_to_shared(&sAl[a_row][a_col]);
    const int b_rb = wn*32 + (lane & 7) + ((lane >> 4) << 3);
    const int b_cb = ((lane >> 3) & 1) * 8;
    const unsigned bBh0 = (unsigned)__cvta_generic_to_shared(&sBh[b_rb][b_cb]);
    const unsigned bBl0 = (unsigned)__cvta_generic_to_shared(&sBl[b_rb][b_cb]);
    const unsigned tstep = 16*BSTR*2;

    const __nv_bfloat16* pAh = &Ah[(long)(m0 + lrow)*K + lk8];
    const __nv_bfloat16* pAl = &Al[(long)(m0 + lrow)*K + lk8];
    const __nv_bfloat16* pBh = &Bh[(long)(n0 + lrow)*K + lk8];
    const __nv_bfloat16* pBl = &Bl[(long)(n0 + lrow)*K + lk8];

    float acc[4][4] = {};
    uint4 rah = *(const uint4*)&pAh[0], ral = *(const uint4*)&pAl[0];
    uint4 rbh = *(const uint4*)&pBh[0], rbl = *(const uint4*)&pBl[0];

    for (int k0 = 0; k0 < K; k0 += 32) {
        *(uint4*)&sAh[lrow][lk8] = rah; *(uint4*)&sAl[lrow][lk8] = ral;
        *(uint4*)&sBh[lrow][lk8] = rbh; *(uint4*)&sBl[lrow][lk8] = rbl;
        __syncthreads();
        if (k0 + 32 < K) {
            rah = *(const uint4*)&pAh[k0+32]; ral = *(const uint4*)&pAl[k0+32];
            rbh = *(const uint4*)&pBh[k0+32]; rbl = *(const uint4*)&pBl[k0+32];
        }
        #pragma unroll
        for (int kk = 0; kk < 2; kk++) {
            const unsigned koff = kk*32;
            unsigned ah[4], al[4];
            ldsm4(ah, aAh + koff);
            ldsm4(al, aAl + koff);
            #pragma unroll
            for (int t = 0; t < 2; t++) {
                unsigned bh[4], bl[4];
                ldsm4(bh, bBh0 + t*tstep + koff);
                ldsm4(bl, bBl0 + t*tstep + koff);
                mma_bf16(acc[2*t],   ah, bh[0], bh[1]);
                mma_bf16(acc[2*t],   al, bh[0], bh[1]);
                mma_bf16(acc[2*t],   ah, bl[0], bl[1]);
                mma_bf16(acc[2*t+1], ah, bh[2], bh[3]);
                mma_bf16(acc[2*t+1], al, bh[2], bh[3]);
                mma_bf16(acc[2*t+1], ah, bl[2], bl[3]);
            }
        }
        __syncthreads();
    }

    #pragma unroll
    for (int nt = 0; nt < 4; nt++) {
        int n = n0 + wn*32 + nt*8 + c4*2;
        float bx = 0.f, by = 0.f;
        if (bias) { bx = bias[n]; by = bias[n+1]; }
        int row0 = m0 + wm*16 + r4, row1 = row0 + 8;
        float v00 = acc[nt][0]+bx, v01 = acc[nt][1]+by;
        float v10 = acc[nt][2]+bx, v11 = acc[nt][3]+by;
        if (pos) {
            const float* p0 = pos + (long)(row0 % SEQ)*DIM + n;
            const float* p1 = pos + (long)(row1 % SEQ)*DIM + n;
            v00 += p0[0]; v01 += p0[1]; v10 += p1[0]; v11 += p1[1];
        }
        if (Cf) {
            *(float2*)&Cf[(long)row0*N + n] = make_float2(v00, v01);
            *(float2*)&Cf[(long)row1*N + n] = make_float2(v10, v11);
        }
        if (Ch) {
            __nv_bfloat162 h0, l0, h1, l1;
            splitbf(v00, h0.x, l0.x); splitbf(v01, h0.y, l0.y);
            splitbf(v10, h1.x, l1.x); splitbf(v11, h1.y, l1.y);
            *(__nv_bfloat162*)&Ch[(long)row0*N + n] = h0;
            *(__nv_bfloat162*)&Cl[(long)row0*N + n] = l0;
            *(__nv_bfloat162*)&Ch[(long)row1*N + n] = h1;
            *(__nv_bfloat162*)&Cl[(long)row1*N + n] = l1;
        }
    }
}

// ---------------- fused attention: bf16x3 QK^T via ldmatrix, staged Q ----------------
#define KROW 40
#define QROW 264
#define VSTR 292
// bytes: K 2*576*40*2 = 92160; V 2*32*292*4 = 74752; Q 2*32*264*2 = 33792; scal 1280
#define ATTN_SMEM (92160 + 74752 + 33792 + 1280)   // 201,984 B

__global__ __launch_bounds__(512, 1) void attn_mma(
    const float* __restrict__ qkv, float* __restrict__ attn_out, int layer)
{
    extern __shared__ float sm[];
    __nv_bfloat16* sKh = (__nv_bfloat16*)sm;             // [576][40]
    __nv_bfloat16* sKl = sKh + 576*KROW;
    unsigned* Vh = (unsigned*)(sKl + 576*KROW);          // [32][292] bf16 pairs
    unsigned* Vl = Vh + 32*VSTR;
    __nv_bfloat16* sQh = (__nv_bfloat16*)(Vl + 32*VSTR); // [32][264]
    __nv_bfloat16* sQl = sQh + 32*QROW;
    float* pbufA  = (float*)(sQl + 32*QROW);             // [32][8]
    float* rowmax = pbufA + 256;                         // [32]
    float* rinv   = rowmax + 32;                         // [32]
    float* buf    = (float*)sKh;                         // PV scratch overlay (32 KB)

    const int tid  = threadIdx.x;
    const int lane = tid & 31;
    const int w    = tid >> 5;                  // 0..15
    const int r4   = lane >> 2;
    const int c4   = lane & 3;
    const int ws   = w >> 3;                    // q-subtile (16 q)
    const int wk   = w & 7;                     // key-slice (72 keys)
    const int qt   = blockIdx.x;                // 0..17
    const int nb   = blockIdx.y;                // 0..31
    const float SC = 0.17677669529663687f;      // 1/sqrt(32)

    // P1 K copy: plane x 576 keys x 4 chunks
    const int kp   = tid >> 8, krem = tid & 255;
    // P1 V copy: plane x 32 rows x 8 chunks
    const int vp   = tid >> 8, vrem = tid & 255;
    const int vdh  = vrem >> 3, vci = vrem & 7;
    // ldmatrix bases
    const unsigned aQh = (unsigned)__cvta_generic_to_shared(
        &sQh[(ws*16 + (lane & 15))*QROW + (lane >> 4)*8]);
    const unsigned aQl = (unsigned)__cvta_generic_to_shared(
        &sQl[(ws*16 + (lane & 15))*QROW + (lane >> 4)*8]);
    const int bkey = wk*72 + (lane & 7) + ((lane >> 4) << 3);
    const unsigned bKh = (unsigned)__cvta_generic_to_shared(
        &sKh[bkey*KROW + ((lane >> 3) & 1)*8]);
    const unsigned bKl = (unsigned)__cvta_generic_to_shared(
        &sKl[bkey*KROW + ((lane >> 3) & 1)*8]);
    const int tkey = wk*72 + 64 + (lane & 7);
    const unsigned tKh = (unsigned)__cvta_generic_to_shared(
        &sKh[tkey*KROW + ((lane >> 3) & 1)*8]);
    const unsigned tKl = (unsigned)__cvta_generic_to_shared(
        &sKl[tkey*KROW + ((lane >> 3) & 1)*8]);
    const unsigned vb_h = (unsigned)__cvta_generic_to_shared(&Vh[lane*VSTR + wk*36]);
    const unsigned vb_l = (unsigned)__cvta_generic_to_shared(&Vl[lane*VSTR + wk*36]);

    // ---- stage Q (scaled, bf16 hi/lo) for all heads, once ----
    {
        const float* qsrc = qkv + (long)(nb*SEQ + qt*32)*768;
        #pragma unroll
        for (int i = 0; i < 4; i++) {
            int f = tid + i*512;               // 0..2047
            int q = f >> 6, d4 = (f & 63)*4;
            float4 v = *(const float4*)&qsrc[(long)q*768 + d4];
            __nv_bfloat162 h01, l01, h23, l23;
            splitbf(v.x*SC, h01.x, l01.x); splitbf(v.y*SC, h01.y, l01.y);
            splitbf(v.z*SC, h23.x, l23.x); splitbf(v.w*SC, h23.y, l23.y);
            *(__nv_bfloat162*)&sQh[q*QROW + d4]     = h01;
            *(__nv_bfloat162*)&sQh[q*QROW + d4 + 2] = h23;
            *(__nv_bfloat162*)&sQl[q*QROW + d4]     = l01;
            *(__nv_bfloat162*)&sQl[q*QROW + d4 + 2] = l23;
        }
    }

    float am[9][4];
    #pragma unroll
    for (int nt = 0; nt < 9; nt++)
        #pragma unroll
        for (int i = 0; i < 4; i++) am[nt][i] = 0.f;

    for (int h = 0; h < NHEAD; h++) {
        // ---- P1: cp.async K (group 0) then V (group 1); wait K only ----
        {
            const long kvb = (long)(nb*NHEAD + h);
            const __nv_bfloat16* gK = (kp ? g_kbl : g_kbh) + kvb*SEQ*32;
            __nv_bfloat16* dK = (kp ? sKl : sKh);
            #pragma unroll
            for (int j = 0; j < 9; j++) {
                int idx = krem + j*256;        // 0..2303
                int key = idx >> 2, ch = (idx & 3)*8;
                cp16(&dK[key*KROW + ch], &gK[key*32 + ch]);
            }
            asm volatile("cp.async.commit_group;\n");
            const __nv_bfloat16* gV = (vp ? g_vtl : g_vth) + kvb*32*SEQ + (long)vdh*SEQ;
            unsigned* dV = (vp ? Vl : Vh) + vdh*VSTR;
            #pragma unroll
            for (int j = 0; j < 9; j++) {
                int cc = vci + j*8;
                cp16(&dV[cc*4], &gV[cc*8]);
            }
            asm volatile("cp.async.commit_group;\n");
            asm volatile("cp.async.wait_group 1;\n");
        }
        __syncthreads();                        // S1

        // ---- P2: S = Q K^T, bf16x3 via ldmatrix ----
        float acc[9][4];
        #pragma unroll
        for (int nt = 0; nt < 9; nt++)
            #pragma unroll
            for (int i = 0; i < 4; i++) acc[nt][i] = 0.f;

        #pragma unroll
        for (int ks = 0; ks < 2; ks++) {
            const unsigned qoff = (h*32 + ks*16)*2;
            unsigned qh[4], ql[4];
            ldsm4(qh, aQh + qoff);
            ldsm4(ql, aQl + qoff);
            const unsigned koff = ks*32;
            #pragma unroll
            for (int g = 0; g < 4; g++) {
                unsigned bh[4], bl[4];
                ldsm4(bh, bKh + g*16*KROW*2 + koff);
                ldsm4(bl, bKl + g*16*KROW*2 + koff);
                mma_bf16(acc[2*g],   qh, bh[0], bh[1]);
                mma_bf16(acc[2*g],   ql, bh[0], bh[1]);
                mma_bf16(acc[2*g],   qh, bl[0], bl[1]);
                mma_bf16(acc[2*g+1], qh, bh[2], bh[3]);
                mma_bf16(acc[2*g+1], ql, bh[2], bh[3]);
                mma_bf16(acc[2*g+1], qh, bl[2], bl[3]);
            }
            {   // tail keys 64..71
                unsigned bh[2], bl[2];
                ldsm2(bh, tKh + koff);
                ldsm2(bl, tKl + koff);
                mma_bf16(acc[8], qh, bh[0], bh[1]);
                mma_bf16(acc[8], ql, bh[0], bh[1]);
                mma_bf16(acc[8], qh, bl[0], bl[1]);
            }
        }
        // partial row max
        {
            float pm[2] = {-1e30f, -1e30f};
            #pragma unroll
            for (int nt = 0; nt < 9; nt++) {
                pm[0] = fmaxf(pm[0], fmaxf(acc[nt][0], acc[nt][1]));
                pm[1] = fmaxf(pm[1], fmaxf(acc[nt][2], acc[nt][3]));
            }
            #pragma unroll
            for (int s = 0; s < 2; s++) {
                pm[s] = fmaxf(pm[s], __shfl_xor_sync(0xffffffffu, pm[s], 1));
                pm[s] = fmaxf(pm[s], __shfl_xor_sync(0xffffffffu, pm[s], 2));
            }
            if (c4 == 0) {
                pbufA[(ws*16 + r4)*8 + wk]     = pm[0];
                pbufA[(ws*16 + 8 + r4)*8 + wk] = pm[1];
            }
        }
        __syncthreads();                        // S2
        if (tid < 32) {
            float m = pbufA[tid*8];
            #pragma unroll
            for (int i = 1; i < 8; i++) m = fmaxf(m, pbufA[tid*8 + i]);
            rowmax[tid] = m;
        }
        __syncthreads();                        // S3
        // ---- P4: e = exp(s - rowmax) in registers; row sums ----
        {
            float rm0 = rowmax[ws*16 + r4], rm1 = rowmax[ws*16 + 8 + r4];
            float ps[2] = {0.f, 0.f};
            #pragma unroll
            for (int nt = 0; nt < 9; nt++) {
                float e0 = __expf(acc[nt][0] - rm0);
                float e1 = __expf(acc[nt][1] - rm0);
                float e2 = __expf(acc[nt][2] - rm1);
                float e3 = __expf(acc[nt][3] - rm1);
                acc[nt][0] = e0; acc[nt][1] = e1;
                acc[nt][2] = e2; acc[nt][3] = e3;
                ps[0] += e0 + e1;
                ps[1] += e2 + e3;
            }
            #pragma unroll
            for (int s = 0; s < 2; s++) {
                ps[s] += __shfl_xor_sync(0xffffffffu, ps[s], 1);
                ps[s] += __shfl_xor_sync(0xffffffffu, ps[s], 2);
            }
            if (c4 == 0) {
                pbufA[(ws*16 + r4)*8 + wk]     = ps[0];
                pbufA[(ws*16 + 8 + r4)*8 + wk] = ps[1];
            }
        }
        __syncthreads();                        // S4
        if (tid < 32) {
            float sa = 0.f;
            #pragma unroll
            for (int i = 0; i < 8; i++) sa += pbufA[tid*8 + i];
            rinv[tid] = __frcp_rn(sa);
        }
        asm volatile("cp.async.wait_group 0;\n");   // V resident
        __syncthreads();                        // S5
        // ---- P5: Am += e * rinv / 8 (registers) ----
        {
            float ra0 = rinv[ws*16 + r4]*0.125f, ra1 = rinv[ws*16 + 8 + r4]*0.125f;
            #pragma unroll
            for (int nt = 0; nt < 9; nt++) {
                am[nt][0] += acc[nt][0] * ra0;
                am[nt][1] += acc[nt][1] * ra0;
                am[nt][2] += acc[nt][2] * ra1;
                am[nt][3] += acc[nt][3] * ra1;
            }
        }
        // ---- pack E into bf16 hi/lo fragments ----
        unsigned eh[9][2], el[9][2];
        #pragma unroll
        for (int nt = 0; nt < 9; nt++) {
            __nv_bfloat162 h01 = __floats2bfloat162_rn(acc[nt][0], acc[nt][1]);
            __nv_bfloat162 h23 = __floats2bfloat162_rn(acc[nt][2], acc[nt][3]);
            __nv_bfloat162 l01 = __floats2bfloat162_rn(acc[nt][0] - __bfloat162float(h01.x),
                                                       acc[nt][1] - __bfloat162float(h01.y));
            __nv_bfloat162 l23 = __floats2bfloat162_rn(acc[nt][2] - __bfloat162float(h23.x),
                                                       acc[nt][3] - __bfloat162float(h23.y));
            eh[nt][0] = *(unsigned*)&h01; eh[nt][1] = *(unsigned*)&h23;
            el[nt][0] = *(unsigned*)&l01; el[nt][1] = *(unsigned*)&l23;
        }
        // ---- PV via ldmatrix: partial O[16q x 32dh] over this warp's 72 keys ----
        float po[4][4] = {};
        #pragma unroll
        for (int s = 0; s < 4; s++) {
            unsigned a_h[4] = {eh[2*s][0], eh[2*s][1], eh[2*s+1][0], eh[2*s+1][1]};
            unsigned a_l[4] = {el[2*s][0], el[2*s][1], el[2*s+1][0], el[2*s+1][1]};
            unsigned bh0[4], bh1[4], bl0[4], bl1[4];
            ldsm4(bh0, vb_h + s*32);
            ldsm4(bh1, vb_h + s*32 + 16);
            ldsm4(bl0, vb_l + s*32);
            ldsm4(bl1, vb_l + s*32 + 16);
            #pragma unroll
            for (int nt6 = 0; nt6 < 4; nt6++) {
                mma_bf16(po[nt6], a_h, bh0[nt6], bh1[nt6]);
                mma_bf16(po[nt6], a_l, bh0[nt6], bh1[nt6]);
                mma_bf16(po[nt6], a_h, bl0[nt6], bl1[nt6]);
            }
        }
        {   // tail keys 64..71 (k8)
            unsigned bh0[4], bl0[4];
            ldsm4(bh0, vb_h + 128);
            ldsm4(bl0, vb_l + 128);
            #pragma unroll
            for (int nt6 = 0; nt6 < 4; nt6++) {
                mma_bf16_k8(po[nt6], eh[8], bh0[nt6]);
                mma_bf16_k8(po[nt6], el[8], bh0[nt6]);
                mma_bf16_k8(po[nt6], eh[8], bl0[nt6]);
            }
        }
        // ---- store partials into buf (K overlay; K reads done since S2) ----
        #pragma unroll
        for (int nt6 = 0; nt6 < 4; nt6++)
            *(float4*)&buf[(((ws*4 + nt6)*8 + wk)*32 + lane)*4] =
                make_float4(po[nt6][0], po[nt6][1], po[nt6][2], po[nt6][3]);
        __syncthreads();                        // S6
        // ---- reduce 8 key-slices; scale; write split bf16 O ----
        if (w < 8) {
            int rws = w >> 2, rnt = w & 3;
            float4 s4 = make_float4(0.f, 0.f, 0.f, 0.f);
            #pragma unroll
            for (int k = 0; k < 8; k++) {
                float4 p = *(const float4*)&buf[(((rws*4 + rnt)*8 + k)*32 + lane)*4];
                s4.x += p.x; s4.y += p.y; s4.z += p.z; s4.w += p.w;
            }
            int q0 = rws*16 + r4;
            int dh = rnt*8 + c4*2;
            float ri0 = rinv[q0], ri1 = rinv[q0 + 8];
            float x0 = s4.x*ri0, x1 = s4.y*ri0;
            float x2 = s4.z*ri1, x3 = s4.w*ri1;
            long orow = (long)(nb*SEQ + qt*32 + q0)*DIM + h*32 + dh;
            __nv_bfloat162 h0, l0, h1, l1;
            splitbf(x0, h0.x, l0.x); splitbf(x1, h0.y, l0.y);
            splitbf(x2, h1.x, l1.x); splitbf(x3, h1.y, l1.y);
            *(__nv_bfloat162*)&g_oh[orow]         = h0;
            *(__nv_bfloat162*)&g_ol[orow]         = l0;
            *(__nv_bfloat162*)&g_oh[orow + 8*DIM] = h1;
            *(__nv_bfloat162*)&g_ol[orow + 8*DIM] = l1;
        }
        __syncthreads();                        // S7
    }
    // ---- final: head-mean attention from registers ----
    float* aout = attn_out + (long)(layer*NB + nb)*SEQ*SEQ + (long)qt*32*SEQ;
    #pragma unroll
    for (int nt = 0; nt < 9; nt++) {
        int col = wk*72 + nt*8 + c4*2;
        *(float2*)&aout[(long)(ws*16 + r4)*SEQ + col]     = make_float2(am[nt][0], am[nt][1]);
        *(float2*)&aout[(long)(ws*16 + 8 + r4)*SEQ + col] = make_float2(am[nt][2], am[nt][3]);
    }
}

// ---------------- feature mean over sequence ----------------
__global__ void feat_k(void) {
    int ni = blockIdx.x, b = blockIdx.y, d = threadIdx.x;
    const float* p = g_pe + ((long)(ni*BATCH + b)*SEQ)*DIM + d;
    float s = 0.f;
    for (int t = 0; t < SEQ; t++) s += p[(long)t*DIM];
    g_feat[b*(NIMG*DIM) + ni*DIM + d] = s * (1.0f/576.0f);
}

// ---------------- MLP head ----------------
__global__ void head_k(const float* __restrict__ w1, const float* __restrict__ b1,
                       const float* __restrict__ w2, const float* __restrict__ b2,
                       float* __restrict__ out) {
    __shared__ float fs[NIMG*DIM];
    __shared__ float hs[MLPDIM];
    int b = blockIdx.x, tid = threadIdx.x;
    for (int t = tid; t < NIMG*DIM; t += MLPDIM) fs[t] = g_feat[b*NIMG*DIM + t];
    __syncthreads();
    float a = b1[tid];
    const float* wr = w1 + (long)tid*(NIMG*DIM);
    for (int d2 = 0; d2 < NIMG*DIM; d2++) a += fs[d2]*wr[d2];
    hs[tid] = fmaxf(a, 0.f) * w2[tid];
    __syncthreads();
    for (int st = 256; st > 0; st >>= 1) {
        if (tid < st) hs[tid] += hs[tid + st];
        __syncthreads();
    }
    if (tid == 0) out[b] = hs[0] + b2[0];
}

// ---------------- launch ----------------
extern "C" void kernel_launch(void* const* d_in, const int* in_sizes, int n_in,
                              void* d_out, int out_size) {
    const float* x      = (const float*)d_in[0];
    const float* conv_w = (const float*)d_in[1];
    const float* conv_b = (const float*)d_in[2];
    const float* pos_e  = (const float*)d_in[3];
    const float* in_w   = (const float*)d_in[4];
    const float* in_b   = (const float*)d_in[5];
    const float* out_w  = (const float*)d_in[6];
    const float* out_b  = (const float*)d_in[7];
    const float* hw1    = (const float*)d_in[8];
    const float* hb1    = (const float*)d_in[9];
    const float* hw2    = (const float*)d_in[10];
    const float* hb2    = (const float*)d_in[11];

    float* out  = (float*)d_out;            // [8]
    float* attn = out + BATCH;              // [6,4,8,576,576]

    cudaFuncSetAttribute(attn_mma, cudaFuncAttributeMaxDynamicSharedMemorySize, ATTN_SMEM);

    __nv_bfloat16 *imh_p, *iml_p, *peh_p, *pel_p, *oh_p, *ol_p;
    __nv_bfloat16 *cwh_p, *cwl_p, *iwh_p, *iwl_p, *owh_p, *owl_p;
    float *qkv_p, *pe_p;
    cudaGetSymbolAddress((void**)&imh_p, g_imh);
    cudaGetSymbolAddress((void**)&iml_p, g_iml);
    cudaGetSymbolAddress((void**)&peh_p, g_peh);
    cudaGetSymbolAddress((void**)&pel_p, g_pel);
    cudaGetSymbolAddress((void**)&oh_p,  g_oh);
    cudaGetSymbolAddress((void**)&ol_p,  g_ol);
    cudaGetSymbolAddress((void**)&cwh_p, g_cwh);
    cudaGetSymbolAddress((void**)&cwl_p, g_cwl);
    cudaGetSymbolAddress((void**)&iwh_p, g_iwh);
    cudaGetSymbolAddress((void**)&iwl_p, g_iwl);
    cudaGetSymbolAddress((void**)&owh_p, g_owh);
    cudaGetSymbolAddress((void**)&owl_p, g_owl);
    cudaGetSymbolAddress((void**)&qkv_p, g_qkv);
    cudaGetSymbolAddress((void**)&pe_p,  g_pe);

    // 0) weight splits
    cvt_bf<<<(NIMG*DIM*KPATCH + 255)/256, 256>>>(conv_w, cwh_p, cwl_p, NIMG*DIM*KPATCH);
    cvt_bf<<<(NLAYER*3*DIM*DIM + 255)/256, 256>>>(in_w, iwh_p, iwl_p, NLAYER*3*DIM*DIM);
    cvt_bf<<<(NLAYER*DIM*DIM + 255)/256, 256>>>(out_w, owh_p, owl_p, NLAYER*DIM*DIM);

    // 1) im2col (split)
    {
        dim3 g(KPATCH/256, SEQ, NB);
        im2col_k<<<g, 256>>>(x);
    }
    // 2) patch-embed GEMM per image (+conv_b +pos) -> peh/pel
    {
        dim3 g(DIM/64, (BATCH*SEQ)/64, NIMG);
        gemm_bf3<<<g, 256>>>(imh_p, iml_p, cwh_p, cwl_p,
                             nullptr, peh_p, pel_p,
                             BATCH*SEQ, DIM, KPATCH,
                             conv_b, pos_e,
                             (long)BATCH*SEQ*KPATCH, (long)DIM*KPATCH,
                             (long)BATCH*SEQ*DIM, DIM);
    }
    // 3) transformer layers
    for (int l = 0; l < NLAYER; l++) {
        {   // qkv: (peh,pel) x in_w -> f32 qkv
            dim3 g((3*DIM)/64, TOK/64, 1);
            gemm_bf3<<<g, 256>>>(peh_p, pel_p,
                                 iwh_p + (long)l*3*DIM*DIM, iwl_p + (long)l*3*DIM*DIM,
                                 qkv_p, nullptr, nullptr,
                                 TOK, 3*DIM, DIM,
                                 in_b + (long)l*3*DIM, nullptr, 0, 0, 0, 0);
        }
        {   // K/V convert
            dim3 g(NHEAD, NB);
            cvt_kv<<<g, 256>>>(qkv_p);
        }
        {
            dim3 g(SEQ/32, NB, 1);
            attn_mma<<<g, 512, ATTN_SMEM>>>(qkv_p, attn, l);
        }
        {   // out-proj: (oh,ol) x out_w -> pe f32 + peh/pel
            dim3 g(DIM/64, TOK/64, 1);
            gemm_bf3<<<g, 256>>>(oh_p, ol_p,
                                 owh_p + (long)l*DIM*DIM, owl_p + (long)l*DIM*DIM,
                                 pe_p, peh_p, pel_p,
                                 TOK, DIM, DIM,
                                 out_b + (long)l*DIM, nullptr, 0, 0, 0, 0);
        }
    }
    // 4) sequence-mean features + MLP head
    {
        dim3 g(NIMG, BATCH);
        feat_k<<<g, DIM>>>();
    }
    head_k<<<BATCH, MLPDIM>>>(hw1, hb1, hw2, hb2, out);
}